// round 6
// baseline (speedup 1.0000x reference)
#include <cuda_runtime.h>
#include <cuda_bf16.h>
#include <cstdint>
#include <math.h>

// ---------------------------------------------------------------------------
// CT-GRU cell: B=2048, U=512, M=8, D=512, fused=1024
// Round 5: HMMA split-bf16 GEMMs (K'=3072), 64x64 warp tiles, fused epilogues:
//   GEMM_R -> retrieval softmax + q_input (writes split-bf16 A' for GEMM_D)
//   GEMM_U -> plain store of ln_tau_s
//   GEMM_D -> tanh + update softmax + decay + h_next/h_hat_next outputs
// ---------------------------------------------------------------------------

#define BB 2048
#define UU 512
#define MM 8
#define DD 512
#define FD 1024
#define RU 4096          // U*M
#define KTOT 3072        // 3 * FD (split-K)

#define LN_TAU_STEP 1.1512925464970229f

// ---------------- scratch (allocation-free device globals) -----------------
__device__ __nv_bfloat16 g_Af[(size_t)BB * KTOT];     // fused'  [B, 3072]
__device__ __nv_bfloat16 g_Ar[(size_t)BB * KTOT];     // reset'  [B, 3072]
__device__ __nv_bfloat16 g_Wr[(size_t)RU * KTOT];     // W_r'^T  [4096, 3072]
__device__ __nv_bfloat16 g_Wu[(size_t)RU * KTOT];     // W_u'^T  [4096, 3072]
__device__ __nv_bfloat16 g_Wd[(size_t)UU * KTOT];     // W_d'^T  [512, 3072]
__device__ float g_u[(size_t)BB * RU];                // ln_tau_s (+bias)

// ---------------------------- asm helpers ----------------------------------
__device__ __forceinline__ uint32_t smem_u32(const void* p) {
    uint32_t a;
    asm("{ .reg .u64 t; cvta.to.shared.u64 t, %1; cvt.u32.u64 %0, t; }"
        : "=r"(a) : "l"(p));
    return a;
}

__device__ __forceinline__ void ldsm_x4(uint32_t* r, uint32_t addr) {
    asm volatile("ldmatrix.sync.aligned.m8n8.x4.shared.b16 {%0,%1,%2,%3}, [%4];"
        : "=r"(r[0]), "=r"(r[1]), "=r"(r[2]), "=r"(r[3]) : "r"(addr));
}

__device__ __forceinline__ void mma_bf16(float* d, const uint32_t* a,
                                         uint32_t b0, uint32_t b1) {
    asm volatile("mma.sync.aligned.m16n8k16.row.col.f32.bf16.bf16.f32 "
        "{%0,%1,%2,%3}, {%4,%5,%6,%7}, {%8,%9}, {%0,%1,%2,%3};"
        : "+f"(d[0]), "+f"(d[1]), "+f"(d[2]), "+f"(d[3])
        : "r"(a[0]), "r"(a[1]), "r"(a[2]), "r"(a[3]), "r"(b0), "r"(b1));
}

__device__ __forceinline__ void cp16(uint32_t dst, const void* src) {
    asm volatile("cp.async.cg.shared.global [%0], [%1], 16;"
                 :: "r"(dst), "l"(src));
}
#define CP_COMMIT() asm volatile("cp.async.commit_group;" ::: "memory")
#define CP_WAIT(n)  asm volatile("cp.async.wait_group %0;" :: "n"(n) : "memory")

// ---------------------------------------------------------------------------
// prep: h = sum_m h_hat; write fused'=[x|h] and reset' inputs-part as bf16
// ---------------------------------------------------------------------------
__global__ void prep_kernel(const float* __restrict__ inputs,
                            const float* __restrict__ state)
{
    int idx = blockIdx.x * blockDim.x + threadIdx.x;
    if (idx >= BB * UU) return;
    int b = idx >> 9;
    int j = idx & 511;

    float x = inputs[(size_t)b * DD + j];
    __nv_bfloat16 xh = __float2bfloat16_rn(x);
    __nv_bfloat16 xl = __float2bfloat16_rn(x - __bfloat162float(xh));

    size_t base = (size_t)b * KTOT;
    g_Af[base + j]        = xh;
    g_Af[base + 1024 + j] = xh;
    g_Af[base + 2048 + j] = xl;
    g_Ar[base + j]        = xh;
    g_Ar[base + 1024 + j] = xh;
    g_Ar[base + 2048 + j] = xl;

    const float* hp = state + (size_t)b * RU + j * MM;
    float4 h0 = *(const float4*)(hp);
    float4 h1 = *(const float4*)(hp + 4);
    float h = ((h0.x + h0.y) + (h0.z + h0.w)) + ((h1.x + h1.y) + (h1.z + h1.w));
    __nv_bfloat16 hh = __float2bfloat16_rn(h);
    __nv_bfloat16 hl = __float2bfloat16_rn(h - __bfloat162float(hh));
    g_Af[base + 512 + j]        = hh;
    g_Af[base + 1024 + 512 + j] = hh;
    g_Af[base + 2048 + 512 + j] = hl;
}

// ---------------------------------------------------------------------------
// weight convert + transpose: W[1024, Ndim] fp32 -> Wt[Ndim, 3072] bf16
// segments [hi | lo | hi]
// ---------------------------------------------------------------------------
__global__ void wconv_kernel(const float* __restrict__ W,
                             __nv_bfloat16* __restrict__ Wt, int Ndim)
{
    __shared__ float t[32][33];
    int n0 = blockIdx.x * 32;
    int k0 = blockIdx.y * 32;
    int tx = threadIdx.x, ty = threadIdx.y;

#pragma unroll
    for (int i = 0; i < 4; i++) {
        int k = k0 + ty + i * 8;
        t[ty + i * 8][tx] = W[(size_t)k * Ndim + n0 + tx];
    }
    __syncthreads();

#pragma unroll
    for (int i = 0; i < 4; i++) {
        int r = ty + i * 8;
        float v = t[tx][r];
        __nv_bfloat16 vh = __float2bfloat16_rn(v);
        __nv_bfloat16 vl = __float2bfloat16_rn(v - __bfloat162float(vh));
        size_t base = (size_t)(n0 + r) * KTOT + k0 + tx;
        Wt[base]        = vh;
        Wt[base + 1024] = vl;
        Wt[base + 2048] = vh;
    }
}

// ---------------------------------------------------------------------------
// Fused HMMA GEMM: BM=128, BN=256, BK=64, 256 threads (8 warps 2x4),
// warp tile 64x64. Double-buffered cp.async, XOR-swizzled 128B rows.
// EPI: 0 = plain store (+bias), 1 = retrieval gate, 2 = final update
// ---------------------------------------------------------------------------
#define GBM 128
#define GBN 256
#define GBK 64
#define NIT (KTOT / GBK)              // 48
#define STG_A 16384u                  // 128 * 128B
#define STG_B 32768u                  // 256 * 128B
#define STG   (STG_A + STG_B)         // 49152
#define GEMM_SMEM (2u * STG)          // 98304

__device__ __forceinline__ uint32_t swz(int row, int chunk) {
    return (uint32_t)(row * 128 + ((chunk ^ (row & 7)) << 4));
}

template<int EPI>
__global__ void __launch_bounds__(256, 1)
gemm_fused_kernel(const __nv_bfloat16* __restrict__ A,
                  const __nv_bfloat16* __restrict__ Bt,
                  const float* __restrict__ bias,
                  float* __restrict__ Cout,          // EPI 0
                  const float* __restrict__ xin,     // EPI 2: ln_tau_s
                  const float* __restrict__ state,   // EPI 1,2
                  const float* __restrict__ elapsed, // EPI 2
                  __nv_bfloat16* __restrict__ Ar,    // EPI 1
                  float* __restrict__ out_h,         // EPI 2
                  float* __restrict__ out_hh,        // EPI 2
                  int Ndim)
{
    extern __shared__ char smem[];
    const uint32_t sb = smem_u32(smem);
    const int tid = threadIdx.x;
    const int wid = tid >> 5;
    const int lane = tid & 31;
    const int bn = blockIdx.x * GBN;
    const int bm = blockIdx.y * GBM;

    const int warp_m = (wid & 1) * 64;      // 0,64
    const int warp_n = (wid >> 1) * 64;     // 0,64,128,192

    float acc[4][8][4];
#pragma unroll
    for (int i = 0; i < 4; i++)
#pragma unroll
        for (int j = 0; j < 8; j++)
#pragma unroll
            for (int v = 0; v < 4; v++) acc[i][j][v] = 0.0f;

    // ---- stage loader: 3072 granules of 16B, 12 per thread ----
    auto load_stage = [&](int it, int buf) {
        const int k0 = it * GBK;
        const uint32_t abase = sb + (uint32_t)buf * STG;
        const uint32_t bbase = abase + STG_A;
#pragma unroll
        for (int g = tid; g < 3072; g += 256) {
            if (g < 1024) {
                int row = g >> 3, ch = g & 7;
                cp16(abase + swz(row, ch),
                     A + (size_t)(bm + row) * KTOT + k0 + ch * 8);
            } else {
                int g2 = g - 1024;
                int row = g2 >> 3, ch = g2 & 7;
                cp16(bbase + swz(row, ch),
                     Bt + (size_t)(bn + row) * KTOT + k0 + ch * 8);
            }
        }
        CP_COMMIT();
    };

    load_stage(0, 0);

#pragma unroll 1
    for (int it = 0; it < NIT; it++) {
        if (it + 1 < NIT) load_stage(it + 1, (it + 1) & 1);
        if (it + 1 < NIT) { CP_WAIT(1); } else { CP_WAIT(0); }
        __syncthreads();

        const uint32_t abase = sb + (uint32_t)(it & 1) * STG;
        const uint32_t bbase = abase + STG_A;

#pragma unroll
        for (int kk = 0; kk < 4; kk++) {
            const int kch = kk * 2;
            uint32_t a[4][4];
#pragma unroll
            for (int mi = 0; mi < 4; mi++) {
                int row = warp_m + mi * 16 + (lane & 15);
                int ch = kch + (lane >> 4);
                ldsm_x4(a[mi], abase + swz(row, ch));
            }
            uint32_t b[4][4];
#pragma unroll
            for (int nb = 0; nb < 4; nb++) {
                int row = warp_n + nb * 16 + (lane & 7) + (((lane >> 4) & 1) << 3);
                int ch = kch + ((lane >> 3) & 1);
                ldsm_x4(b[nb], bbase + swz(row, ch));
            }
#pragma unroll
            for (int mi = 0; mi < 4; mi++)
#pragma unroll
                for (int nb = 0; nb < 4; nb++) {
                    mma_bf16(acc[mi][nb * 2 + 0], a[mi], b[nb][0], b[nb][1]);
                    mma_bf16(acc[mi][nb * 2 + 1], a[mi], b[nb][2], b[nb][3]);
                }
        }
        __syncthreads();
    }

    const int q  = lane & 3;
    const int rq = lane >> 2;

    if (EPI == 0) {
        // ---- plain store with bias ----
#pragma unroll
        for (int ni = 0; ni < 8; ni++) {
            int col = bn + warp_n + ni * 8 + q * 2;
            float bv0 = bias[col], bv1 = bias[col + 1];
#pragma unroll
            for (int mi = 0; mi < 4; mi++) {
                int r0 = bm + warp_m + mi * 16 + rq;
                float2 v0 = make_float2(acc[mi][ni][0] + bv0, acc[mi][ni][1] + bv1);
                float2 v1 = make_float2(acc[mi][ni][2] + bv0, acc[mi][ni][3] + bv1);
                *(float2*)(Cout + (size_t)r0 * Ndim + col) = v0;
                *(float2*)(Cout + (size_t)(r0 + 8) * Ndim + col) = v1;
            }
        }
    } else if (EPI == 1) {
        // ---- retrieval gate: softmax over 8 buckets (one lane quad), q_input ----
        const float t0 = LN_TAU_STEP * (float)(q * 2);
        const float t1 = LN_TAU_STEP * (float)(q * 2 + 1);
#pragma unroll
        for (int ni = 0; ni < 8; ni++) {
            int colb = bn + warp_n + ni * 8;
            int u = colb >> 3;
            float bv0 = bias[colb + q * 2], bv1 = bias[colb + q * 2 + 1];
#pragma unroll
            for (int mi = 0; mi < 4; mi++) {
#pragma unroll
                for (int hf = 0; hf < 2; hf++) {
                    int r = bm + warp_m + mi * 16 + rq + hf * 8;
                    float x0 = acc[mi][ni][hf * 2 + 0] + bv0;
                    float x1 = acc[mi][ni][hf * 2 + 1] + bv1;
                    float d0 = x0 - t0, d1 = x1 - t1;
                    float e0 = -d0 * d0, e1 = -d1 * d1;
                    float mx = fmaxf(e0, e1);
                    mx = fmaxf(mx, __shfl_xor_sync(0xffffffffu, mx, 1));
                    mx = fmaxf(mx, __shfl_xor_sync(0xffffffffu, mx, 2));
                    float w0 = __expf(e0 - mx), w1 = __expf(e1 - mx);
                    float2 hv = *(const float2*)(state + (size_t)r * RU + u * 8 + q * 2);
                    float s  = w0 + w1;
                    float qs = w0 * hv.x + w1 * hv.y;
                    s  += __shfl_xor_sync(0xffffffffu, s, 1);
                    qs += __shfl_xor_sync(0xffffffffu, qs, 1);
                    s  += __shfl_xor_sync(0xffffffffu, s, 2);
                    qs += __shfl_xor_sync(0xffffffffu, qs, 2);
                    if (q == 0) {
                        float qv = qs / s;
                        __nv_bfloat16 qh = __float2bfloat16_rn(qv);
                        __nv_bfloat16 ql = __float2bfloat16_rn(qv - __bfloat162float(qh));
                        size_t base = (size_t)r * KTOT;
                        Ar[base + 512 + u]  = qh;
                        Ar[base + 1536 + u] = qh;
                        Ar[base + 2560 + u] = ql;
                    }
                }
            }
        }
    } else {
        // ---- final update: qk=tanh(dpre); ski softmax; decay; outputs ----
        const float invtau[8] = {1.0f, 0.31622776601683794f, 0.1f,
                                 0.03162277660168379f, 0.01f,
                                 0.003162277660168379f, 0.001f,
                                 0.00031622776601683794f};
#pragma unroll
        for (int ni = 0; ni < 8; ni++) {
            int u0 = bn + warp_n + ni * 8 + q * 2;
            float bv0 = bias[u0], bv1 = bias[u0 + 1];
#pragma unroll
            for (int mi = 0; mi < 4; mi++) {
#pragma unroll
                for (int hf = 0; hf < 2; hf++) {
                    int r = bm + warp_m + mi * 16 + rq + hf * 8;
                    float el = __ldg(elapsed + r);
#pragma unroll
                    for (int t = 0; t < 2; t++) {
                        int u = u0 + t;
                        float dpre = acc[mi][ni][hf * 2 + t] + (t ? bv1 : bv0);
                        float qk = tanhf(dpre);
                        const float* xp = xin + (size_t)r * RU + u * 8;
                        const float* hp = state + (size_t)r * RU + u * 8;
                        float x[8], h[8];
                        *(float4*)&x[0] = *(const float4*)(xp);
                        *(float4*)&x[4] = *(const float4*)(xp + 4);
                        *(float4*)&h[0] = *(const float4*)(hp);
                        *(float4*)&h[4] = *(const float4*)(hp + 4);
                        float e[8], mx = -1e30f;
#pragma unroll
                        for (int c = 0; c < 8; c++) {
                            float d = x[c] - LN_TAU_STEP * (float)c;
                            e[c] = -d * d;
                            mx = fmaxf(mx, e[c]);
                        }
                        float w[8], s = 0.0f;
#pragma unroll
                        for (int c = 0; c < 8; c++) {
                            w[c] = __expf(e[c] - mx);
                            s += w[c];
                        }
                        float inv_s = 1.0f / s;
                        float hh[8], hn = 0.0f;
#pragma unroll
                        for (int c = 0; c < 8; c++) {
                            float ski = w[c] * inv_s;
                            float dec = __expf(-el * invtau[c]);
                            hh[c] = ((1.0f - ski) * h[c] + ski * qk) * dec;
                            hn += hh[c];
                        }
                        float* op = out_hh + (size_t)r * RU + u * 8;
                        *(float4*)(op)     = *(const float4*)&hh[0];
                        *(float4*)(op + 4) = *(const float4*)&hh[4];
                        if (out_h) out_h[(size_t)r * UU + u] = hn;
                    }
                }
            }
        }
    }
}

// ---------------------------------------------------------------------------
// launch
// ---------------------------------------------------------------------------
extern "C" void kernel_launch(void* const* d_in, const int* in_sizes, int n_in,
                              void* d_out, int out_size)
{
    const float* inputs  = (const float*)d_in[0];
    const float* elapsed = (const float*)d_in[1];
    const float* state   = (const float*)d_in[2];
    const float* W_r     = (const float*)d_in[3];
    const float* b_r     = (const float*)d_in[4];
    const float* W_d     = (const float*)d_in[5];
    const float* b_d     = (const float*)d_in[6];
    const float* W_u     = (const float*)d_in[7];
    const float* b_u     = (const float*)d_in[8];

    float* out = (float*)d_out;
    float* out_h;
    float* out_hh;
    if (out_size == BB * UU * MM) {
        out_h = nullptr;
        out_hh = out;
    } else {
        out_h = out;
        out_hh = out + (size_t)BB * UU;
    }

    __nv_bfloat16 *p_Af, *p_Ar, *p_Wr, *p_Wu, *p_Wd;
    float *p_u;
    cudaGetSymbolAddress((void**)&p_Af, g_Af);
    cudaGetSymbolAddress((void**)&p_Ar, g_Ar);
    cudaGetSymbolAddress((void**)&p_Wr, g_Wr);
    cudaGetSymbolAddress((void**)&p_Wu, g_Wu);
    cudaGetSymbolAddress((void**)&p_Wd, g_Wd);
    cudaGetSymbolAddress((void**)&p_u,  g_u);

    cudaFuncSetAttribute(gemm_fused_kernel<0>,
                         cudaFuncAttributeMaxDynamicSharedMemorySize, GEMM_SMEM);
    cudaFuncSetAttribute(gemm_fused_kernel<1>,
                         cudaFuncAttributeMaxDynamicSharedMemorySize, GEMM_SMEM);
    cudaFuncSetAttribute(gemm_fused_kernel<2>,
                         cudaFuncAttributeMaxDynamicSharedMemorySize, GEMM_SMEM);

    const int ew_blocks = (BB * UU + 255) / 256;
    dim3 tb(32, 8);

    prep_kernel<<<ew_blocks, 256>>>(inputs, state);
    wconv_kernel<<<dim3(RU / 32, 32), tb>>>(W_r, p_Wr, RU);
    wconv_kernel<<<dim3(RU / 32, 32), tb>>>(W_u, p_Wu, RU);
    wconv_kernel<<<dim3(UU / 32, 32), tb>>>(W_d, p_Wd, UU);

    // R: retrieval gate fused (writes q into g_Ar split segments)
    gemm_fused_kernel<1><<<dim3(RU / GBN, BB / GBM), 256, GEMM_SMEM>>>(
        p_Af, p_Wr, b_r, nullptr, nullptr, state, nullptr, p_Ar,
        nullptr, nullptr, RU);

    // U: plain store of ln_tau_s (+bias)
    gemm_fused_kernel<0><<<dim3(RU / GBN, BB / GBM), 256, GEMM_SMEM>>>(
        p_Af, p_Wu, b_u, p_u, nullptr, nullptr, nullptr, nullptr,
        nullptr, nullptr, RU);

    // D: tanh + update gate + decay + outputs fused
    gemm_fused_kernel<2><<<dim3(UU / GBN, BB / GBM), 256, GEMM_SMEM>>>(
        p_Ar, p_Wd, b_d, nullptr, p_u, state, elapsed, nullptr,
        out_h, out_hh, UU);
}

// round 10
// speedup vs baseline: 1.2129x; 1.2129x over previous
#include <cuda_runtime.h>
#include <cuda_bf16.h>
#include <cstdint>
#include <math.h>

// ---------------------------------------------------------------------------
// CT-GRU cell: B=2048, U=512, M=8, D=512, fused=1024
// Round 6: round-3 proven HMMA mainloop (BM=256,BN=128,16 warps,64x32 warp
// tile) + round-5 fused epilogues:
//   GEMM_R -> retrieval softmax + q_input (writes split-bf16 A' for GEMM_D)
//   GEMM_U -> plain store of ln_tau_s
//   GEMM_D -> tanh + update softmax + decay + h_next/h_hat_next outputs
// ---------------------------------------------------------------------------

#define BB 2048
#define UU 512
#define MM 8
#define DD 512
#define FD 1024
#define RU 4096          // U*M
#define KTOT 3072        // 3 * FD (split-K)

#define LN_TAU_STEP 1.1512925464970229f

// ---------------- scratch (allocation-free device globals) -----------------
__device__ __nv_bfloat16 g_Af[(size_t)BB * KTOT];     // fused'  [B, 3072]
__device__ __nv_bfloat16 g_Ar[(size_t)BB * KTOT];     // reset'  [B, 3072]
__device__ __nv_bfloat16 g_Wr[(size_t)RU * KTOT];     // W_r'^T  [4096, 3072]
__device__ __nv_bfloat16 g_Wu[(size_t)RU * KTOT];     // W_u'^T  [4096, 3072]
__device__ __nv_bfloat16 g_Wd[(size_t)UU * KTOT];     // W_d'^T  [512, 3072]
__device__ float g_u[(size_t)BB * RU];                // ln_tau_s (+bias)

// ---------------------------- asm helpers ----------------------------------
__device__ __forceinline__ uint32_t smem_u32(const void* p) {
    uint32_t a;
    asm("{ .reg .u64 t; cvta.to.shared.u64 t, %1; cvt.u32.u64 %0, t; }"
        : "=r"(a) : "l"(p));
    return a;
}

__device__ __forceinline__ void ldsm_x4(uint32_t* r, uint32_t addr) {
    asm volatile("ldmatrix.sync.aligned.m8n8.x4.shared.b16 {%0,%1,%2,%3}, [%4];"
        : "=r"(r[0]), "=r"(r[1]), "=r"(r[2]), "=r"(r[3]) : "r"(addr));
}

__device__ __forceinline__ void mma_bf16(float* d, const uint32_t* a,
                                         uint32_t b0, uint32_t b1) {
    asm volatile("mma.sync.aligned.m16n8k16.row.col.f32.bf16.bf16.f32 "
        "{%0,%1,%2,%3}, {%4,%5,%6,%7}, {%8,%9}, {%0,%1,%2,%3};"
        : "+f"(d[0]), "+f"(d[1]), "+f"(d[2]), "+f"(d[3])
        : "r"(a[0]), "r"(a[1]), "r"(a[2]), "r"(a[3]), "r"(b0), "r"(b1));
}

__device__ __forceinline__ void cp16(uint32_t dst, const void* src) {
    asm volatile("cp.async.cg.shared.global [%0], [%1], 16;"
                 :: "r"(dst), "l"(src));
}
#define CP_COMMIT() asm volatile("cp.async.commit_group;" ::: "memory")
#define CP_WAIT(n)  asm volatile("cp.async.wait_group %0;" :: "n"(n) : "memory")

// ---------------------------------------------------------------------------
// prep: h = sum_m h_hat; write fused'=[x|h] and reset' inputs-part as bf16
// ---------------------------------------------------------------------------
__global__ void prep_kernel(const float* __restrict__ inputs,
                            const float* __restrict__ state)
{
    int idx = blockIdx.x * blockDim.x + threadIdx.x;
    if (idx >= BB * UU) return;
    int b = idx >> 9;
    int j = idx & 511;

    float x = inputs[(size_t)b * DD + j];
    __nv_bfloat16 xh = __float2bfloat16_rn(x);
    __nv_bfloat16 xl = __float2bfloat16_rn(x - __bfloat162float(xh));

    size_t base = (size_t)b * KTOT;
    g_Af[base + j]        = xh;
    g_Af[base + 1024 + j] = xh;
    g_Af[base + 2048 + j] = xl;
    g_Ar[base + j]        = xh;
    g_Ar[base + 1024 + j] = xh;
    g_Ar[base + 2048 + j] = xl;

    const float* hp = state + (size_t)b * RU + j * MM;
    float4 h0 = *(const float4*)(hp);
    float4 h1 = *(const float4*)(hp + 4);
    float h = ((h0.x + h0.y) + (h0.z + h0.w)) + ((h1.x + h1.y) + (h1.z + h1.w));
    __nv_bfloat16 hh = __float2bfloat16_rn(h);
    __nv_bfloat16 hl = __float2bfloat16_rn(h - __bfloat162float(hh));
    g_Af[base + 512 + j]        = hh;
    g_Af[base + 1024 + 512 + j] = hh;
    g_Af[base + 2048 + 512 + j] = hl;
}

// ---------------------------------------------------------------------------
// weight convert + transpose: W[1024, Ndim] fp32 -> Wt[Ndim, 3072] bf16
// segments [hi | lo | hi]
// ---------------------------------------------------------------------------
__global__ void wconv_kernel(const float* __restrict__ W,
                             __nv_bfloat16* __restrict__ Wt, int Ndim)
{
    __shared__ float t[32][33];
    int n0 = blockIdx.x * 32;
    int k0 = blockIdx.y * 32;
    int tx = threadIdx.x, ty = threadIdx.y;

#pragma unroll
    for (int i = 0; i < 4; i++) {
        int k = k0 + ty + i * 8;
        t[ty + i * 8][tx] = W[(size_t)k * Ndim + n0 + tx];
    }
    __syncthreads();

#pragma unroll
    for (int i = 0; i < 4; i++) {
        int r = ty + i * 8;
        float v = t[tx][r];
        __nv_bfloat16 vh = __float2bfloat16_rn(v);
        __nv_bfloat16 vl = __float2bfloat16_rn(v - __bfloat162float(vh));
        size_t base = (size_t)(n0 + r) * KTOT + k0 + tx;
        Wt[base]        = vh;
        Wt[base + 1024] = vl;
        Wt[base + 2048] = vh;
    }
}

// ---------------------------------------------------------------------------
// Fused HMMA GEMM: BM=256, BN=128, BK=64, 512 threads (16 warps 4x4),
// warp tile 64x32. Double-buffered cp.async, XOR-swizzled 128B rows.
// EPI: 0 = plain store (+bias), 1 = retrieval gate, 2 = final update
// ---------------------------------------------------------------------------
#define GBM 256
#define GBN 128
#define GBK 64
#define NIT (KTOT / GBK)              // 48
#define STG_A 32768u                  // 256 * 128B
#define STG_B 16384u                  // 128 * 128B
#define STG   (STG_A + STG_B)         // 49152
#define GEMM_SMEM (2u * STG)          // 98304

__device__ __forceinline__ uint32_t swz(int row, int chunk) {
    return (uint32_t)(row * 128 + ((chunk ^ (row & 7)) << 4));
}

template<int EPI>
__global__ void __launch_bounds__(512, 1)
gemm_fused_kernel(const __nv_bfloat16* __restrict__ A,
                  const __nv_bfloat16* __restrict__ Bt,
                  const float* __restrict__ bias,
                  float* __restrict__ Cout,          // EPI 0
                  const float* __restrict__ xin,     // EPI 2: ln_tau_s
                  const float* __restrict__ state,   // EPI 1,2
                  const float* __restrict__ elapsed, // EPI 2
                  __nv_bfloat16* __restrict__ Ar,    // EPI 1
                  float* __restrict__ out_h,         // EPI 2
                  float* __restrict__ out_hh,        // EPI 2
                  int Ndim)
{
    extern __shared__ char smem[];
    const uint32_t sb = smem_u32(smem);
    const int tid = threadIdx.x;
    const int wid = tid >> 5;
    const int lane = tid & 31;
    const int bn = blockIdx.x * GBN;
    const int bm = blockIdx.y * GBM;

    const int warp_m = (wid & 3) * 64;      // 0,64,128,192
    const int warp_n = (wid >> 2) * 32;     // 0,32,64,96

    float acc[4][4][4];
#pragma unroll
    for (int i = 0; i < 4; i++)
#pragma unroll
        for (int j = 0; j < 4; j++)
#pragma unroll
            for (int v = 0; v < 4; v++) acc[i][j][v] = 0.0f;

    // ---- stage loader: 3072 granules of 16B, 6 per thread ----
    auto load_stage = [&](int it, int buf) {
        const int k0 = it * GBK;
        const uint32_t abase = sb + (uint32_t)buf * STG;
        const uint32_t bbase = abase + STG_A;
#pragma unroll
        for (int g = tid; g < 3072; g += 512) {
            if (g < 2048) {
                int row = g >> 3, ch = g & 7;
                cp16(abase + swz(row, ch),
                     A + (size_t)(bm + row) * KTOT + k0 + ch * 8);
            } else {
                int g2 = g - 2048;
                int row = g2 >> 3, ch = g2 & 7;
                cp16(bbase + swz(row, ch),
                     Bt + (size_t)(bn + row) * KTOT + k0 + ch * 8);
            }
        }
        CP_COMMIT();
    };

    load_stage(0, 0);

#pragma unroll 1
    for (int it = 0; it < NIT; it++) {
        if (it + 1 < NIT) load_stage(it + 1, (it + 1) & 1);
        if (it + 1 < NIT) { CP_WAIT(1); } else { CP_WAIT(0); }
        __syncthreads();

        const uint32_t abase = sb + (uint32_t)(it & 1) * STG;
        const uint32_t bbase = abase + STG_A;

#pragma unroll
        for (int kk = 0; kk < 4; kk++) {            // k-steps of 16
            const int kch = kk * 2;
            uint32_t a[4][4];
#pragma unroll
            for (int mi = 0; mi < 4; mi++) {
                int row = warp_m + mi * 16 + (lane & 15);
                int ch = kch + ((lane >> 4) & 1);
                ldsm_x4(a[mi], abase + swz(row, ch));
            }
#pragma unroll
            for (int nb = 0; nb < 2; nb++) {
                uint32_t b[4];
                int row = warp_n + nb * 16 + (lane & 7) + (((lane >> 4) & 1) << 3);
                int ch = kch + ((lane >> 3) & 1);
                ldsm_x4(b, bbase + swz(row, ch));
#pragma unroll
                for (int mi = 0; mi < 4; mi++) {
                    mma_bf16(acc[mi][nb * 2 + 0], a[mi], b[0], b[1]);
                    mma_bf16(acc[mi][nb * 2 + 1], a[mi], b[2], b[3]);
                }
            }
        }
        __syncthreads();
    }

    const int q  = lane & 3;
    const int rq = lane >> 2;

    if (EPI == 0) {
        // ---- plain store with bias ----
#pragma unroll
        for (int ni = 0; ni < 4; ni++) {
            int col = bn + warp_n + ni * 8 + q * 2;
            float bv0 = bias[col], bv1 = bias[col + 1];
#pragma unroll
            for (int mi = 0; mi < 4; mi++) {
                int r0 = bm + warp_m + mi * 16 + rq;
                float2 v0 = make_float2(acc[mi][ni][0] + bv0, acc[mi][ni][1] + bv1);
                float2 v1 = make_float2(acc[mi][ni][2] + bv0, acc[mi][ni][3] + bv1);
                *(float2*)(Cout + (size_t)r0 * Ndim + col) = v0;
                *(float2*)(Cout + (size_t)(r0 + 8) * Ndim + col) = v1;
            }
        }
    } else if (EPI == 1) {
        // ---- retrieval gate: softmax over 8 buckets (one lane quad), q_input ----
        const float t0 = LN_TAU_STEP * (float)(q * 2);
        const float t1 = LN_TAU_STEP * (float)(q * 2 + 1);
#pragma unroll
        for (int ni = 0; ni < 4; ni++) {
            int colb = bn + warp_n + ni * 8;
            int u = colb >> 3;
            float bv0 = bias[colb + q * 2], bv1 = bias[colb + q * 2 + 1];
#pragma unroll
            for (int mi = 0; mi < 4; mi++) {
#pragma unroll
                for (int hf = 0; hf < 2; hf++) {
                    int r = bm + warp_m + mi * 16 + rq + hf * 8;
                    float x0 = acc[mi][ni][hf * 2 + 0] + bv0;
                    float x1 = acc[mi][ni][hf * 2 + 1] + bv1;
                    float d0 = x0 - t0, d1 = x1 - t1;
                    float e0 = -d0 * d0, e1 = -d1 * d1;
                    float mx = fmaxf(e0, e1);
                    mx = fmaxf(mx, __shfl_xor_sync(0xffffffffu, mx, 1));
                    mx = fmaxf(mx, __shfl_xor_sync(0xffffffffu, mx, 2));
                    float w0 = __expf(e0 - mx), w1 = __expf(e1 - mx);
                    float2 hv = *(const float2*)(state + (size_t)r * RU + u * 8 + q * 2);
                    float s  = w0 + w1;
                    float qs = w0 * hv.x + w1 * hv.y;
                    s  += __shfl_xor_sync(0xffffffffu, s, 1);
                    qs += __shfl_xor_sync(0xffffffffu, qs, 1);
                    s  += __shfl_xor_sync(0xffffffffu, s, 2);
                    qs += __shfl_xor_sync(0xffffffffu, qs, 2);
                    if (q == 0) {
                        float qv = qs / s;
                        __nv_bfloat16 qh = __float2bfloat16_rn(qv);
                        __nv_bfloat16 ql = __float2bfloat16_rn(qv - __bfloat162float(qh));
                        size_t base = (size_t)r * KTOT;
                        Ar[base + 512 + u]  = qh;
                        Ar[base + 1536 + u] = qh;
                        Ar[base + 2560 + u] = ql;
                    }
                }
            }
        }
    } else {
        // ---- final update: qk=tanh(dpre); ski softmax; decay; outputs ----
        const float invtau[8] = {1.0f, 0.31622776601683794f, 0.1f,
                                 0.03162277660168379f, 0.01f,
                                 0.003162277660168379f, 0.001f,
                                 0.00031622776601683794f};
#pragma unroll
        for (int ni = 0; ni < 4; ni++) {
            int u0 = bn + warp_n + ni * 8 + q * 2;
            float bv0 = bias[u0], bv1 = bias[u0 + 1];
#pragma unroll
            for (int mi = 0; mi < 4; mi++) {
#pragma unroll
                for (int hf = 0; hf < 2; hf++) {
                    int r = bm + warp_m + mi * 16 + rq + hf * 8;
                    float el = __ldg(elapsed + r);
#pragma unroll
                    for (int t = 0; t < 2; t++) {
                        int u = u0 + t;
                        float dpre = acc[mi][ni][hf * 2 + t] + (t ? bv1 : bv0);
                        float qk = tanhf(dpre);
                        const float* xp = xin + (size_t)r * RU + u * 8;
                        const float* hp = state + (size_t)r * RU + u * 8;
                        float x[8], h[8];
                        *(float4*)&x[0] = *(const float4*)(xp);
                        *(float4*)&x[4] = *(const float4*)(xp + 4);
                        *(float4*)&h[0] = *(const float4*)(hp);
                        *(float4*)&h[4] = *(const float4*)(hp + 4);
                        float e[8], mx = -1e30f;
#pragma unroll
                        for (int c = 0; c < 8; c++) {
                            float d = x[c] - LN_TAU_STEP * (float)c;
                            e[c] = -d * d;
                            mx = fmaxf(mx, e[c]);
                        }
                        float w[8], s = 0.0f;
#pragma unroll
                        for (int c = 0; c < 8; c++) {
                            w[c] = __expf(e[c] - mx);
                            s += w[c];
                        }
                        float inv_s = 1.0f / s;
                        float hh[8], hn = 0.0f;
#pragma unroll
                        for (int c = 0; c < 8; c++) {
                            float ski = w[c] * inv_s;
                            float dec = __expf(-el * invtau[c]);
                            hh[c] = ((1.0f - ski) * h[c] + ski * qk) * dec;
                            hn += hh[c];
                        }
                        float* op = out_hh + (size_t)r * RU + u * 8;
                        *(float4*)(op)     = *(const float4*)&hh[0];
                        *(float4*)(op + 4) = *(const float4*)&hh[4];
                        if (out_h) out_h[(size_t)r * UU + u] = hn;
                    }
                }
            }
        }
    }
}

// ---------------------------------------------------------------------------
// launch
// ---------------------------------------------------------------------------
extern "C" void kernel_launch(void* const* d_in, const int* in_sizes, int n_in,
                              void* d_out, int out_size)
{
    const float* inputs  = (const float*)d_in[0];
    const float* elapsed = (const float*)d_in[1];
    const float* state   = (const float*)d_in[2];
    const float* W_r     = (const float*)d_in[3];
    const float* b_r     = (const float*)d_in[4];
    const float* W_d     = (const float*)d_in[5];
    const float* b_d     = (const float*)d_in[6];
    const float* W_u     = (const float*)d_in[7];
    const float* b_u     = (const float*)d_in[8];

    float* out = (float*)d_out;
    float* out_h;
    float* out_hh;
    if (out_size == BB * UU * MM) {
        out_h = nullptr;
        out_hh = out;
    } else {
        out_h = out;
        out_hh = out + (size_t)BB * UU;
    }

    __nv_bfloat16 *p_Af, *p_Ar, *p_Wr, *p_Wu, *p_Wd;
    float *p_u;
    cudaGetSymbolAddress((void**)&p_Af, g_Af);
    cudaGetSymbolAddress((void**)&p_Ar, g_Ar);
    cudaGetSymbolAddress((void**)&p_Wr, g_Wr);
    cudaGetSymbolAddress((void**)&p_Wu, g_Wu);
    cudaGetSymbolAddress((void**)&p_Wd, g_Wd);
    cudaGetSymbolAddress((void**)&p_u,  g_u);

    cudaFuncSetAttribute(gemm_fused_kernel<0>,
                         cudaFuncAttributeMaxDynamicSharedMemorySize, GEMM_SMEM);
    cudaFuncSetAttribute(gemm_fused_kernel<1>,
                         cudaFuncAttributeMaxDynamicSharedMemorySize, GEMM_SMEM);
    cudaFuncSetAttribute(gemm_fused_kernel<2>,
                         cudaFuncAttributeMaxDynamicSharedMemorySize, GEMM_SMEM);

    const int ew_blocks = (BB * UU + 255) / 256;
    dim3 tb(32, 8);

    prep_kernel<<<ew_blocks, 256>>>(inputs, state);
    wconv_kernel<<<dim3(RU / 32, 32), tb>>>(W_r, p_Wr, RU);
    wconv_kernel<<<dim3(RU / 32, 32), tb>>>(W_u, p_Wu, RU);
    wconv_kernel<<<dim3(UU / 32, 32), tb>>>(W_d, p_Wd, UU);

    // R: retrieval gate fused (writes q into g_Ar split segments)
    gemm_fused_kernel<1><<<dim3(RU / GBN, BB / GBM), 512, GEMM_SMEM>>>(
        p_Af, p_Wr, b_r, nullptr, nullptr, state, nullptr, p_Ar,
        nullptr, nullptr, RU);

    // U: plain store of ln_tau_s (+bias)
    gemm_fused_kernel<0><<<dim3(RU / GBN, BB / GBM), 512, GEMM_SMEM>>>(
        p_Af, p_Wu, b_u, p_u, nullptr, nullptr, nullptr, nullptr,
        nullptr, nullptr, RU);

    // D: tanh + update gate + decay + outputs fused
    gemm_fused_kernel<2><<<dim3(UU / GBN, BB / GBM), 512, GEMM_SMEM>>>(
        p_Ar, p_Wd, b_d, nullptr, p_u, state, elapsed, nullptr,
        out_h, out_hh, UU);
}

// round 11
// speedup vs baseline: 1.2632x; 1.0414x over previous
#include <cuda_runtime.h>
#include <cuda_bf16.h>
#include <cstdint>
#include <math.h>

// ---------------------------------------------------------------------------
// CT-GRU cell: B=2048, U=512, M=8, D=512, fused=1024
// Round 7: round-3 HMMA mainloop (BM=256,BN=128,16 warps,64x32 warp tile)
// + fused epilogues with COALESCED staging:
//   GEMM_R -> retrieval softmax + q_input, smem-staged, coalesced bf16 writes
//   GEMM_U -> plain store of ln_tau_s
//   GEMM_D -> tanh + update softmax + decay + h_next/h_hat_next outputs
// ---------------------------------------------------------------------------

#define BB 2048
#define UU 512
#define MM 8
#define DD 512
#define FD 1024
#define RU 4096          // U*M
#define KTOT 3072        // 3 * FD (split-K)

#define LN_TAU_STEP 1.1512925464970229f

// ---------------- scratch (allocation-free device globals) -----------------
__device__ __nv_bfloat16 g_Af[(size_t)BB * KTOT];     // fused'  [B, 3072]
__device__ __nv_bfloat16 g_Ar[(size_t)BB * KTOT];     // reset'  [B, 3072]
__device__ __nv_bfloat16 g_Wr[(size_t)RU * KTOT];     // W_r'^T  [4096, 3072]
__device__ __nv_bfloat16 g_Wu[(size_t)RU * KTOT];     // W_u'^T  [4096, 3072]
__device__ __nv_bfloat16 g_Wd[(size_t)UU * KTOT];     // W_d'^T  [512, 3072]
__device__ float g_u[(size_t)BB * RU];                // ln_tau_s (+bias)

// ---------------------------- asm helpers ----------------------------------
__device__ __forceinline__ uint32_t smem_u32(const void* p) {
    uint32_t a;
    asm("{ .reg .u64 t; cvta.to.shared.u64 t, %1; cvt.u32.u64 %0, t; }"
        : "=r"(a) : "l"(p));
    return a;
}

__device__ __forceinline__ void ldsm_x4(uint32_t* r, uint32_t addr) {
    asm volatile("ldmatrix.sync.aligned.m8n8.x4.shared.b16 {%0,%1,%2,%3}, [%4];"
        : "=r"(r[0]), "=r"(r[1]), "=r"(r[2]), "=r"(r[3]) : "r"(addr));
}

__device__ __forceinline__ void mma_bf16(float* d, const uint32_t* a,
                                         uint32_t b0, uint32_t b1) {
    asm volatile("mma.sync.aligned.m16n8k16.row.col.f32.bf16.bf16.f32 "
        "{%0,%1,%2,%3}, {%4,%5,%6,%7}, {%8,%9}, {%0,%1,%2,%3};"
        : "+f"(d[0]), "+f"(d[1]), "+f"(d[2]), "+f"(d[3])
        : "r"(a[0]), "r"(a[1]), "r"(a[2]), "r"(a[3]), "r"(b0), "r"(b1));
}

__device__ __forceinline__ void cp16(uint32_t dst, const void* src) {
    asm volatile("cp.async.cg.shared.global [%0], [%1], 16;"
                 :: "r"(dst), "l"(src));
}
#define CP_COMMIT() asm volatile("cp.async.commit_group;" ::: "memory")
#define CP_WAIT(n)  asm volatile("cp.async.wait_group %0;" :: "n"(n) : "memory")

// ---------------------------------------------------------------------------
// prep: h = sum_m h_hat; write fused'=[x|h] and reset' inputs-part as bf16
// ---------------------------------------------------------------------------
__global__ void prep_kernel(const float* __restrict__ inputs,
                            const float* __restrict__ state)
{
    int idx = blockIdx.x * blockDim.x + threadIdx.x;
    if (idx >= BB * UU) return;
    int b = idx >> 9;
    int j = idx & 511;

    float x = inputs[(size_t)b * DD + j];
    __nv_bfloat16 xh = __float2bfloat16_rn(x);
    __nv_bfloat16 xl = __float2bfloat16_rn(x - __bfloat162float(xh));

    size_t base = (size_t)b * KTOT;
    g_Af[base + j]        = xh;
    g_Af[base + 1024 + j] = xh;
    g_Af[base + 2048 + j] = xl;
    g_Ar[base + j]        = xh;
    g_Ar[base + 1024 + j] = xh;
    g_Ar[base + 2048 + j] = xl;

    const float* hp = state + (size_t)b * RU + j * MM;
    float4 h0 = *(const float4*)(hp);
    float4 h1 = *(const float4*)(hp + 4);
    float h = ((h0.x + h0.y) + (h0.z + h0.w)) + ((h1.x + h1.y) + (h1.z + h1.w));
    __nv_bfloat16 hh = __float2bfloat16_rn(h);
    __nv_bfloat16 hl = __float2bfloat16_rn(h - __bfloat162float(hh));
    g_Af[base + 512 + j]        = hh;
    g_Af[base + 1024 + 512 + j] = hh;
    g_Af[base + 2048 + 512 + j] = hl;
}

// ---------------------------------------------------------------------------
// weight convert + transpose: W[1024, Ndim] fp32 -> Wt[Ndim, 3072] bf16
// segments [hi | lo | hi]
// ---------------------------------------------------------------------------
__global__ void wconv_kernel(const float* __restrict__ W,
                             __nv_bfloat16* __restrict__ Wt, int Ndim)
{
    __shared__ float t[32][33];
    int n0 = blockIdx.x * 32;
    int k0 = blockIdx.y * 32;
    int tx = threadIdx.x, ty = threadIdx.y;

#pragma unroll
    for (int i = 0; i < 4; i++) {
        int k = k0 + ty + i * 8;
        t[ty + i * 8][tx] = W[(size_t)k * Ndim + n0 + tx];
    }
    __syncthreads();

#pragma unroll
    for (int i = 0; i < 4; i++) {
        int r = ty + i * 8;
        float v = t[tx][r];
        __nv_bfloat16 vh = __float2bfloat16_rn(v);
        __nv_bfloat16 vl = __float2bfloat16_rn(v - __bfloat162float(vh));
        size_t base = (size_t)(n0 + r) * KTOT + k0 + tx;
        Wt[base]        = vh;
        Wt[base + 1024] = vl;
        Wt[base + 2048] = vh;
    }
}

// ---------------------------------------------------------------------------
// Fused HMMA GEMM: BM=256, BN=128, BK=64, 512 threads (16 warps 4x4),
// warp tile 64x32. Double-buffered cp.async, XOR-swizzled 128B rows.
// EPI: 0 = plain store (+bias), 1 = retrieval gate (coalesced staged writes),
//      2 = final update
// ---------------------------------------------------------------------------
#define GBM 256
#define GBN 128
#define GBK 64
#define NIT (KTOT / GBK)              // 48
#define STG_A 32768u                  // 256 * 128B
#define STG_B 16384u                  // 128 * 128B
#define STG   (STG_A + STG_B)         // 49152
#define GEMM_SMEM (2u * STG)          // 98304

__device__ __forceinline__ uint32_t swz(int row, int chunk) {
    return (uint32_t)(row * 128 + ((chunk ^ (row & 7)) << 4));
}

template<int EPI>
__global__ void __launch_bounds__(512, 1)
gemm_fused_kernel(const __nv_bfloat16* __restrict__ A,
                  const __nv_bfloat16* __restrict__ Bt,
                  const float* __restrict__ bias,
                  float* __restrict__ Cout,          // EPI 0
                  const float* __restrict__ xin,     // EPI 2: ln_tau_s
                  const float* __restrict__ state,   // EPI 1,2
                  const float* __restrict__ elapsed, // EPI 2
                  __nv_bfloat16* __restrict__ Ar,    // EPI 1
                  float* __restrict__ out_h,         // EPI 2
                  float* __restrict__ out_hh,        // EPI 2
                  int Ndim)
{
    extern __shared__ char smem[];
    const uint32_t sb = smem_u32(smem);
    const int tid = threadIdx.x;
    const int wid = tid >> 5;
    const int lane = tid & 31;
    const int bn = blockIdx.x * GBN;
    const int bm = blockIdx.y * GBM;

    const int warp_m = (wid & 3) * 64;      // 0,64,128,192
    const int warp_n = (wid >> 2) * 32;     // 0,32,64,96

    float acc[4][4][4];
#pragma unroll
    for (int i = 0; i < 4; i++)
#pragma unroll
        for (int j = 0; j < 4; j++)
#pragma unroll
            for (int v = 0; v < 4; v++) acc[i][j][v] = 0.0f;

    // ---- stage loader: 3072 granules of 16B, 6 per thread ----
    auto load_stage = [&](int it, int buf) {
        const int k0 = it * GBK;
        const uint32_t abase = sb + (uint32_t)buf * STG;
        const uint32_t bbase = abase + STG_A;
#pragma unroll
        for (int g = tid; g < 3072; g += 512) {
            if (g < 2048) {
                int row = g >> 3, ch = g & 7;
                cp16(abase + swz(row, ch),
                     A + (size_t)(bm + row) * KTOT + k0 + ch * 8);
            } else {
                int g2 = g - 2048;
                int row = g2 >> 3, ch = g2 & 7;
                cp16(bbase + swz(row, ch),
                     Bt + (size_t)(bn + row) * KTOT + k0 + ch * 8);
            }
        }
        CP_COMMIT();
    };

    load_stage(0, 0);

#pragma unroll 1
    for (int it = 0; it < NIT; it++) {
        if (it + 1 < NIT) load_stage(it + 1, (it + 1) & 1);
        if (it + 1 < NIT) { CP_WAIT(1); } else { CP_WAIT(0); }
        __syncthreads();

        const uint32_t abase = sb + (uint32_t)(it & 1) * STG;
        const uint32_t bbase = abase + STG_A;

#pragma unroll
        for (int kk = 0; kk < 4; kk++) {            // k-steps of 16
            const int kch = kk * 2;
            uint32_t a[4][4];
#pragma unroll
            for (int mi = 0; mi < 4; mi++) {
                int row = warp_m + mi * 16 + (lane & 15);
                int ch = kch + ((lane >> 4) & 1);
                ldsm_x4(a[mi], abase + swz(row, ch));
            }
#pragma unroll
            for (int nb = 0; nb < 2; nb++) {
                uint32_t b[4];
                int row = warp_n + nb * 16 + (lane & 7) + (((lane >> 4) & 1) << 3);
                int ch = kch + ((lane >> 3) & 1);
                ldsm_x4(b, bbase + swz(row, ch));
#pragma unroll
                for (int mi = 0; mi < 4; mi++) {
                    mma_bf16(acc[mi][nb * 2 + 0], a[mi], b[0], b[1]);
                    mma_bf16(acc[mi][nb * 2 + 1], a[mi], b[2], b[3]);
                }
            }
        }
        __syncthreads();
    }

    const int q  = lane & 3;
    const int rq = lane >> 2;

    if (EPI == 0) {
        // ---- plain store with bias ----
#pragma unroll
        for (int ni = 0; ni < 4; ni++) {
            int col = bn + warp_n + ni * 8 + q * 2;
            float bv0 = bias[col], bv1 = bias[col + 1];
#pragma unroll
            for (int mi = 0; mi < 4; mi++) {
                int r0 = bm + warp_m + mi * 16 + rq;
                float2 v0 = make_float2(acc[mi][ni][0] + bv0, acc[mi][ni][1] + bv1);
                float2 v1 = make_float2(acc[mi][ni][2] + bv0, acc[mi][ni][3] + bv1);
                *(float2*)(Cout + (size_t)r0 * Ndim + col) = v0;
                *(float2*)(Cout + (size_t)(r0 + 8) * Ndim + col) = v1;
            }
        }
    } else if (EPI == 1) {
        // ---- retrieval gate: softmax over 8 buckets (one lane quad) ----
        // Stage q-values in smem, then coalesced bf16 writes of 16-unit
        // row-slices into the 3 split segments of Ar.
        float* qs = (float*)smem;              // [256][17] padded
        const float t0 = LN_TAU_STEP * (float)(q * 2);
        const float t1 = LN_TAU_STEP * (float)(q * 2 + 1);
#pragma unroll
        for (int ni = 0; ni < 4; ni++) {
            int colb = bn + warp_n + ni * 8;
            int u = colb >> 3;                 // global unit index
            int u_loc = (warp_n >> 3) + ni;    // 0..15 within CTA
            float bv0 = bias[colb + q * 2], bv1 = bias[colb + q * 2 + 1];
#pragma unroll
            for (int mi = 0; mi < 4; mi++) {
#pragma unroll
                for (int hf = 0; hf < 2; hf++) {
                    int r_loc = warp_m + mi * 16 + rq + hf * 8;
                    int r = bm + r_loc;
                    float x0 = acc[mi][ni][hf * 2 + 0] + bv0;
                    float x1 = acc[mi][ni][hf * 2 + 1] + bv1;
                    float d0 = x0 - t0, d1 = x1 - t1;
                    float e0 = -d0 * d0, e1 = -d1 * d1;
                    float mx = fmaxf(e0, e1);
                    mx = fmaxf(mx, __shfl_xor_sync(0xffffffffu, mx, 1));
                    mx = fmaxf(mx, __shfl_xor_sync(0xffffffffu, mx, 2));
                    float w0 = __expf(e0 - mx), w1 = __expf(e1 - mx);
                    float2 hv = *(const float2*)(state + (size_t)r * RU + u * 8 + q * 2);
                    float s  = w0 + w1;
                    float qsum = w0 * hv.x + w1 * hv.y;
                    s    += __shfl_xor_sync(0xffffffffu, s, 1);
                    qsum += __shfl_xor_sync(0xffffffffu, qsum, 1);
                    s    += __shfl_xor_sync(0xffffffffu, s, 2);
                    qsum += __shfl_xor_sync(0xffffffffu, qsum, 2);
                    if (q == 0) qs[r_loc * 17 + u_loc] = qsum / s;
                }
            }
        }
        __syncthreads();
        {
            int r_loc = tid & 255;
            int sel = tid >> 8;                // 0: hi halves, 1: lo halves
            __align__(16) __nv_bfloat16 v16[16];
#pragma unroll
            for (int c = 0; c < 16; c++) {
                float v = qs[r_loc * 17 + c];
                __nv_bfloat16 vh = __float2bfloat16_rn(v);
                v16[c] = sel ? __float2bfloat16_rn(v - __bfloat162float(vh)) : vh;
            }
            size_t base = (size_t)(bm + r_loc) * KTOT + 512 + (bn >> 3);
            const uint4* pv = (const uint4*)v16;
            if (sel == 0) {
                *(uint4*)(Ar + base)            = pv[0];
                *(uint4*)(Ar + base + 8)        = pv[1];
                *(uint4*)(Ar + base + 1024)     = pv[0];
                *(uint4*)(Ar + base + 1024 + 8) = pv[1];
            } else {
                *(uint4*)(Ar + base + 2048)     = pv[0];
                *(uint4*)(Ar + base + 2048 + 8) = pv[1];
            }
        }
    } else {
        // ---- final update: qk=tanh(dpre); ski softmax; decay; outputs ----
        const float invtau[8] = {1.0f, 0.31622776601683794f, 0.1f,
                                 0.03162277660168379f, 0.01f,
                                 0.003162277660168379f, 0.001f,
                                 0.00031622776601683794f};
#pragma unroll
        for (int ni = 0; ni < 4; ni++) {
            int u0 = bn + warp_n + ni * 8 + q * 2;
            float bv0 = bias[u0], bv1 = bias[u0 + 1];
#pragma unroll
            for (int mi = 0; mi < 4; mi++) {
#pragma unroll
                for (int hf = 0; hf < 2; hf++) {
                    int r = bm + warp_m + mi * 16 + rq + hf * 8;
                    float el = __ldg(elapsed + r);
#pragma unroll
                    for (int t = 0; t < 2; t++) {
                        int u = u0 + t;
                        float dpre = acc[mi][ni][hf * 2 + t] + (t ? bv1 : bv0);
                        float qk = tanhf(dpre);
                        const float* xp = xin + (size_t)r * RU + u * 8;
                        const float* hp = state + (size_t)r * RU + u * 8;
                        float x[8], h[8];
                        *(float4*)&x[0] = *(const float4*)(xp);
                        *(float4*)&x[4] = *(const float4*)(xp + 4);
                        *(float4*)&h[0] = *(const float4*)(hp);
                        *(float4*)&h[4] = *(const float4*)(hp + 4);
                        float e[8], mx = -1e30f;
#pragma unroll
                        for (int c = 0; c < 8; c++) {
                            float d = x[c] - LN_TAU_STEP * (float)c;
                            e[c] = -d * d;
                            mx = fmaxf(mx, e[c]);
                        }
                        float w[8], s = 0.0f;
#pragma unroll
                        for (int c = 0; c < 8; c++) {
                            w[c] = __expf(e[c] - mx);
                            s += w[c];
                        }
                        float inv_s = 1.0f / s;
                        float hh[8], hn = 0.0f;
#pragma unroll
                        for (int c = 0; c < 8; c++) {
                            float ski = w[c] * inv_s;
                            float dec = __expf(-el * invtau[c]);
                            hh[c] = ((1.0f - ski) * h[c] + ski * qk) * dec;
                            hn += hh[c];
                        }
                        float* op = out_hh + (size_t)r * RU + u * 8;
                        *(float4*)(op)     = *(const float4*)&hh[0];
                        *(float4*)(op + 4) = *(const float4*)&hh[4];
                        if (out_h) out_h[(size_t)r * UU + u] = hn;
                    }
                }
            }
        }
    }
}

// ---------------------------------------------------------------------------
// launch
// ---------------------------------------------------------------------------
extern "C" void kernel_launch(void* const* d_in, const int* in_sizes, int n_in,
                              void* d_out, int out_size)
{
    const float* inputs  = (const float*)d_in[0];
    const float* elapsed = (const float*)d_in[1];
    const float* state   = (const float*)d_in[2];
    const float* W_r     = (const float*)d_in[3];
    const float* b_r     = (const float*)d_in[4];
    const float* W_d     = (const float*)d_in[5];
    const float* b_d     = (const float*)d_in[6];
    const float* W_u     = (const float*)d_in[7];
    const float* b_u     = (const float*)d_in[8];

    float* out = (float*)d_out;
    float* out_h;
    float* out_hh;
    if (out_size == BB * UU * MM) {
        out_h = nullptr;
        out_hh = out;
    } else {
        out_h = out;
        out_hh = out + (size_t)BB * UU;
    }

    __nv_bfloat16 *p_Af, *p_Ar, *p_Wr, *p_Wu, *p_Wd;
    float *p_u;
    cudaGetSymbolAddress((void**)&p_Af, g_Af);
    cudaGetSymbolAddress((void**)&p_Ar, g_Ar);
    cudaGetSymbolAddress((void**)&p_Wr, g_Wr);
    cudaGetSymbolAddress((void**)&p_Wu, g_Wu);
    cudaGetSymbolAddress((void**)&p_Wd, g_Wd);
    cudaGetSymbolAddress((void**)&p_u,  g_u);

    cudaFuncSetAttribute(gemm_fused_kernel<0>,
                         cudaFuncAttributeMaxDynamicSharedMemorySize, GEMM_SMEM);
    cudaFuncSetAttribute(gemm_fused_kernel<1>,
                         cudaFuncAttributeMaxDynamicSharedMemorySize, GEMM_SMEM);
    cudaFuncSetAttribute(gemm_fused_kernel<2>,
                         cudaFuncAttributeMaxDynamicSharedMemorySize, GEMM_SMEM);

    const int ew_blocks = (BB * UU + 255) / 256;
    dim3 tb(32, 8);

    prep_kernel<<<ew_blocks, 256>>>(inputs, state);
    wconv_kernel<<<dim3(RU / 32, 32), tb>>>(W_r, p_Wr, RU);
    wconv_kernel<<<dim3(RU / 32, 32), tb>>>(W_u, p_Wu, RU);
    wconv_kernel<<<dim3(UU / 32, 32), tb>>>(W_d, p_Wd, UU);

    // R: retrieval gate fused (coalesced staged writes of q into g_Ar)
    gemm_fused_kernel<1><<<dim3(RU / GBN, BB / GBM), 512, GEMM_SMEM>>>(
        p_Af, p_Wr, b_r, nullptr, nullptr, state, nullptr, p_Ar,
        nullptr, nullptr, RU);

    // U: plain store of ln_tau_s (+bias)
    gemm_fused_kernel<0><<<dim3(RU / GBN, BB / GBM), 512, GEMM_SMEM>>>(
        p_Af, p_Wu, b_u, p_u, nullptr, nullptr, nullptr, nullptr,
        nullptr, nullptr, RU);

    // D: tanh + update gate + decay + outputs fused
    gemm_fused_kernel<2><<<dim3(UU / GBN, BB / GBM), 512, GEMM_SMEM>>>(
        p_Ar, p_Wd, b_d, nullptr, p_u, state, elapsed, nullptr,
        out_h, out_hh, UU);
}

// round 12
// speedup vs baseline: 1.5678x; 1.2411x over previous
#include <cuda_runtime.h>
#include <cuda_bf16.h>
#include <cstdint>
#include <math.h>

// ---------------------------------------------------------------------------
// CT-GRU cell: B=2048, U=512, M=8, D=512, fused=1024
// Round 8: round-3 structure (separate elementwise kernels, plain GEMM
// epilogues) + 3-stage cp.async pipeline with ONE __syncthreads per K-iter.
// GEMMs: split-bf16 K'=3072 = [hi|hi|lo] x [hi|lo|hi], mma.sync m16n8k16.
// ---------------------------------------------------------------------------

#define BB 2048
#define UU 512
#define MM 8
#define DD 512
#define FD 1024
#define RU 4096          // U*M
#define KTOT 3072        // 3 * FD (split-K)

#define LN_TAU_STEP 1.1512925464970229f

// ---------------- scratch (allocation-free device globals) -----------------
__device__ __nv_bfloat16 g_Af[(size_t)BB * KTOT];     // fused'  [B, 3072]
__device__ __nv_bfloat16 g_Ar[(size_t)BB * KTOT];     // reset'  [B, 3072]
__device__ __nv_bfloat16 g_Wr[(size_t)RU * KTOT];     // W_r'^T  [4096, 3072]
__device__ __nv_bfloat16 g_Wu[(size_t)RU * KTOT];     // W_u'^T  [4096, 3072]
__device__ __nv_bfloat16 g_Wd[(size_t)UU * KTOT];     // W_d'^T  [512, 3072]
__device__ float g_r[(size_t)BB * RU];                // ln_tau_r
__device__ float g_u[(size_t)BB * RU];                // ln_tau_s
__device__ float g_dpre[(size_t)BB * UU];             // pre-tanh

// ---------------------------- asm helpers ----------------------------------
__device__ __forceinline__ uint32_t smem_u32(const void* p) {
    uint32_t a;
    asm("{ .reg .u64 t; cvta.to.shared.u64 t, %1; cvt.u32.u64 %0, t; }"
        : "=r"(a) : "l"(p));
    return a;
}

__device__ __forceinline__ void ldsm_x4(uint32_t* r, uint32_t addr) {
    asm volatile("ldmatrix.sync.aligned.m8n8.x4.shared.b16 {%0,%1,%2,%3}, [%4];"
        : "=r"(r[0]), "=r"(r[1]), "=r"(r[2]), "=r"(r[3]) : "r"(addr));
}

__device__ __forceinline__ void mma_bf16(float* d, const uint32_t* a,
                                         uint32_t b0, uint32_t b1) {
    asm volatile("mma.sync.aligned.m16n8k16.row.col.f32.bf16.bf16.f32 "
        "{%0,%1,%2,%3}, {%4,%5,%6,%7}, {%8,%9}, {%0,%1,%2,%3};"
        : "+f"(d[0]), "+f"(d[1]), "+f"(d[2]), "+f"(d[3])
        : "r"(a[0]), "r"(a[1]), "r"(a[2]), "r"(a[3]), "r"(b0), "r"(b1));
}

__device__ __forceinline__ void cp16(uint32_t dst, const void* src) {
    asm volatile("cp.async.cg.shared.global [%0], [%1], 16;"
                 :: "r"(dst), "l"(src));
}
#define CP_COMMIT() asm volatile("cp.async.commit_group;" ::: "memory")
#define CP_WAIT(n)  asm volatile("cp.async.wait_group %0;" :: "n"(n) : "memory")

// ---------------------------------------------------------------------------
// prep: h = sum_m h_hat; write fused'=[x|h] and reset' inputs-part as bf16
// ---------------------------------------------------------------------------
__global__ void prep_kernel(const float* __restrict__ inputs,
                            const float* __restrict__ state)
{
    int idx = blockIdx.x * blockDim.x + threadIdx.x;
    if (idx >= BB * UU) return;
    int b = idx >> 9;
    int j = idx & 511;

    float x = inputs[(size_t)b * DD + j];
    __nv_bfloat16 xh = __float2bfloat16_rn(x);
    __nv_bfloat16 xl = __float2bfloat16_rn(x - __bfloat162float(xh));

    size_t base = (size_t)b * KTOT;
    g_Af[base + j]        = xh;
    g_Af[base + 1024 + j] = xh;
    g_Af[base + 2048 + j] = xl;
    g_Ar[base + j]        = xh;
    g_Ar[base + 1024 + j] = xh;
    g_Ar[base + 2048 + j] = xl;

    const float* hp = state + (size_t)b * RU + j * MM;
    float4 h0 = *(const float4*)(hp);
    float4 h1 = *(const float4*)(hp + 4);
    float h = ((h0.x + h0.y) + (h0.z + h0.w)) + ((h1.x + h1.y) + (h1.z + h1.w));
    __nv_bfloat16 hh = __float2bfloat16_rn(h);
    __nv_bfloat16 hl = __float2bfloat16_rn(h - __bfloat162float(hh));
    g_Af[base + 512 + j]        = hh;
    g_Af[base + 1024 + 512 + j] = hh;
    g_Af[base + 2048 + 512 + j] = hl;
}

// ---------------------------------------------------------------------------
// weight convert + transpose: W[1024, Ndim] fp32 -> Wt[Ndim, 3072] bf16
// segments [hi | lo | hi]
// ---------------------------------------------------------------------------
__global__ void wconv_kernel(const float* __restrict__ W,
                             __nv_bfloat16* __restrict__ Wt, int Ndim)
{
    __shared__ float t[32][33];
    int n0 = blockIdx.x * 32;
    int k0 = blockIdx.y * 32;
    int tx = threadIdx.x, ty = threadIdx.y;

#pragma unroll
    for (int i = 0; i < 4; i++) {
        int k = k0 + ty + i * 8;
        t[ty + i * 8][tx] = W[(size_t)k * Ndim + n0 + tx];
    }
    __syncthreads();

#pragma unroll
    for (int i = 0; i < 4; i++) {
        int r = ty + i * 8;
        float v = t[tx][r];
        __nv_bfloat16 vh = __float2bfloat16_rn(v);
        __nv_bfloat16 vl = __float2bfloat16_rn(v - __bfloat162float(vh));
        size_t base = (size_t)(n0 + r) * KTOT + k0 + tx;
        Wt[base]        = vh;
        Wt[base + 1024] = vl;
        Wt[base + 2048] = vh;
    }
}

// ---------------------------------------------------------------------------
// HMMA GEMM: C[2048, Ndim] = A'[2048,3072] @ Bt'[Ndim,3072]^T + bias
// BM=256, BN=128, BK=64, 512 threads (16 warps 4x4), warp tile 64x32.
// 3-stage cp.async pipeline, ONE __syncthreads per iteration,
// XOR-swizzled 128B rows for conflict-free ldmatrix.
// ---------------------------------------------------------------------------
#define GBM 256
#define GBN 128
#define GBK 64
#define NIT (KTOT / GBK)              // 48
#define STG_A 32768u                  // 256 * 128B
#define STG_B 16384u                  // 128 * 128B
#define STG   (STG_A + STG_B)         // 49152
#define NSTAGE 3
#define GEMM_SMEM (NSTAGE * STG)      // 147456

__device__ __forceinline__ uint32_t swz(int row, int chunk) {
    return (uint32_t)(row * 128 + ((chunk ^ (row & 7)) << 4));
}

__global__ void __launch_bounds__(512, 1)
gemm_mma_kernel(const __nv_bfloat16* __restrict__ A,
                const __nv_bfloat16* __restrict__ Bt,
                const float* __restrict__ bias,
                float* __restrict__ C,
                int Ndim)
{
    extern __shared__ char smem[];
    const uint32_t sb = smem_u32(smem);
    const int tid = threadIdx.x;
    const int wid = tid >> 5;
    const int lane = tid & 31;
    const int bn = blockIdx.x * GBN;
    const int bm = blockIdx.y * GBM;

    const int warp_m = (wid & 3) * 64;      // 0,64,128,192
    const int warp_n = (wid >> 2) * 32;     // 0,32,64,96

    float acc[4][4][4];
#pragma unroll
    for (int i = 0; i < 4; i++)
#pragma unroll
        for (int j = 0; j < 4; j++)
#pragma unroll
            for (int v = 0; v < 4; v++) acc[i][j][v] = 0.0f;

    // ---- stage loader: 3072 granules of 16B, 6 per thread ----
    auto load_stage = [&](int it) {
        const int k0 = it * GBK;
        const uint32_t abase = sb + (uint32_t)(it % NSTAGE) * STG;
        const uint32_t bbase = abase + STG_A;
#pragma unroll
        for (int g = tid; g < 3072; g += 512) {
            if (g < 2048) {
                int row = g >> 3, ch = g & 7;
                cp16(abase + swz(row, ch),
                     A + (size_t)(bm + row) * KTOT + k0 + ch * 8);
            } else {
                int g2 = g - 2048;
                int row = g2 >> 3, ch = g2 & 7;
                cp16(bbase + swz(row, ch),
                     Bt + (size_t)(bn + row) * KTOT + k0 + ch * 8);
            }
        }
        CP_COMMIT();
    };

    load_stage(0);
    load_stage(1);

#pragma unroll 1
    for (int it = 0; it < NIT; it++) {
        // stage `it` must be resident; stage `it+1` may still be in flight
        if (it + 1 < NIT) { CP_WAIT(1); } else { CP_WAIT(0); }
        __syncthreads();
        // issue the load 2 stages ahead (its buffer was last read at it-1,
        // which completed before the barrier above)
        if (it + 2 < NIT) load_stage(it + 2);

        const uint32_t abase = sb + (uint32_t)(it % NSTAGE) * STG;
        const uint32_t bbase = abase + STG_A;

#pragma unroll
        for (int kk = 0; kk < 4; kk++) {            // k-steps of 16
            const int kch = kk * 2;
            uint32_t a[4][4];
#pragma unroll
            for (int mi = 0; mi < 4; mi++) {
                int row = warp_m + mi * 16 + (lane & 15);
                int ch = kch + ((lane >> 4) & 1);
                ldsm_x4(a[mi], abase + swz(row, ch));
            }
#pragma unroll
            for (int nb = 0; nb < 2; nb++) {
                uint32_t b[4];
                int row = warp_n + nb * 16 + (lane & 7) + (((lane >> 4) & 1) << 3);
                int ch = kch + ((lane >> 3) & 1);
                ldsm_x4(b, bbase + swz(row, ch));
#pragma unroll
                for (int mi = 0; mi < 4; mi++) {
                    mma_bf16(acc[mi][nb * 2 + 0], a[mi], b[0], b[1]);
                    mma_bf16(acc[mi][nb * 2 + 1], a[mi], b[2], b[3]);
                }
            }
        }
        // no trailing __syncthreads: 3-stage ring guarantees the buffer
        // overwritten by load(it+2) was last read in iteration it-1.
    }

    // ---- epilogue with bias ----
    const int q  = lane & 3;
    const int rq = lane >> 2;
#pragma unroll
    for (int ni = 0; ni < 4; ni++) {
        int col = bn + warp_n + ni * 8 + q * 2;
        float bv0 = bias[col], bv1 = bias[col + 1];
#pragma unroll
        for (int mi = 0; mi < 4; mi++) {
            int r0 = bm + warp_m + mi * 16 + rq;
            float2 v0 = make_float2(acc[mi][ni][0] + bv0, acc[mi][ni][1] + bv1);
            float2 v1 = make_float2(acc[mi][ni][2] + bv0, acc[mi][ni][3] + bv1);
            *(float2*)(C + (size_t)r0 * Ndim + col) = v0;
            *(float2*)(C + (size_t)(r0 + 8) * Ndim + col) = v1;
        }
    }
}

// ---------------------------------------------------------------------------
// gate_r: rki softmax + q_input; writes q (bf16 split) into reset' columns
// ---------------------------------------------------------------------------
__global__ void gate_r_kernel(const float* __restrict__ state)
{
    int idx = blockIdx.x * blockDim.x + threadIdx.x;
    if (idx >= BB * UU) return;
    int b = idx >> 9;
    int u = idx & 511;

    const float* rp = g_r + (size_t)b * RU + u * MM;
    float x[8];
    *(float4*)&x[0] = *(const float4*)(rp);
    *(float4*)&x[4] = *(const float4*)(rp + 4);

    const float* hp = state + (size_t)b * RU + u * MM;
    float h[8];
    *(float4*)&h[0] = *(const float4*)(hp);
    *(float4*)&h[4] = *(const float4*)(hp + 4);

    float e[8], mx = -1e30f;
#pragma unroll
    for (int m = 0; m < 8; m++) {
        float d = x[m] - LN_TAU_STEP * (float)m;
        e[m] = -d * d;
        mx = fmaxf(mx, e[m]);
    }
    float s = 0.0f, q = 0.0f;
#pragma unroll
    for (int m = 0; m < 8; m++) {
        float w = __expf(e[m] - mx);
        s += w;
        q = fmaf(w, h[m], q);
    }
    float qv = q / s;
    __nv_bfloat16 qh = __float2bfloat16_rn(qv);
    __nv_bfloat16 ql = __float2bfloat16_rn(qv - __bfloat162float(qh));
    size_t base = (size_t)b * KTOT;
    g_Ar[base + 512 + u]        = qh;
    g_Ar[base + 1024 + 512 + u] = qh;
    g_Ar[base + 2048 + 512 + u] = ql;
}

// ---------------------------------------------------------------------------
// final: qk = tanh(dpre); ski softmax; decay; outputs
// ---------------------------------------------------------------------------
__global__ void final_kernel(const float* __restrict__ state,
                             const float* __restrict__ elapsed,
                             float* __restrict__ out_h,
                             float* __restrict__ out_hh)
{
    int idx = blockIdx.x * blockDim.x + threadIdx.x;
    if (idx >= BB * UU) return;
    int b = idx >> 9;
    int u = idx & 511;

    const float invtau[8] = {1.0f, 0.31622776601683794f, 0.1f,
                             0.03162277660168379f, 0.01f,
                             0.003162277660168379f, 0.001f,
                             0.00031622776601683794f};

    float qk = tanhf(g_dpre[(size_t)b * UU + u]);

    const float* up = g_u + (size_t)b * RU + u * MM;
    float x[8];
    *(float4*)&x[0] = *(const float4*)(up);
    *(float4*)&x[4] = *(const float4*)(up + 4);

    const float* hp = state + (size_t)b * RU + u * MM;
    float h[8];
    *(float4*)&h[0] = *(const float4*)(hp);
    *(float4*)&h[4] = *(const float4*)(hp + 4);

    float e[8], mx = -1e30f;
#pragma unroll
    for (int m = 0; m < 8; m++) {
        float d = x[m] - LN_TAU_STEP * (float)m;
        e[m] = -d * d;
        mx = fmaxf(mx, e[m]);
    }
    float w[8], s = 0.0f;
#pragma unroll
    for (int m = 0; m < 8; m++) {
        w[m] = __expf(e[m] - mx);
        s += w[m];
    }
    float inv_s = 1.0f / s;
    float el = elapsed[b];

    float hh[8], hn = 0.0f;
#pragma unroll
    for (int m = 0; m < 8; m++) {
        float ski = w[m] * inv_s;
        float dec = __expf(-el * invtau[m]);
        hh[m] = ((1.0f - ski) * h[m] + ski * qk) * dec;
        hn += hh[m];
    }

    float* op = out_hh + (size_t)b * RU + u * MM;
    *(float4*)(op)     = *(const float4*)&hh[0];
    *(float4*)(op + 4) = *(const float4*)&hh[4];
    if (out_h) out_h[(size_t)b * UU + u] = hn;
}

// ---------------------------------------------------------------------------
// launch
// ---------------------------------------------------------------------------
extern "C" void kernel_launch(void* const* d_in, const int* in_sizes, int n_in,
                              void* d_out, int out_size)
{
    const float* inputs  = (const float*)d_in[0];
    const float* elapsed = (const float*)d_in[1];
    const float* state   = (const float*)d_in[2];
    const float* W_r     = (const float*)d_in[3];
    const float* b_r     = (const float*)d_in[4];
    const float* W_d     = (const float*)d_in[5];
    const float* b_d     = (const float*)d_in[6];
    const float* W_u     = (const float*)d_in[7];
    const float* b_u     = (const float*)d_in[8];

    float* out = (float*)d_out;
    float* out_h;
    float* out_hh;
    if (out_size == BB * UU * MM) {
        out_h = nullptr;
        out_hh = out;
    } else {
        out_h = out;
        out_hh = out + (size_t)BB * UU;
    }

    __nv_bfloat16 *p_Af, *p_Ar, *p_Wr, *p_Wu, *p_Wd;
    float *p_r, *p_u, *p_dpre;
    cudaGetSymbolAddress((void**)&p_Af, g_Af);
    cudaGetSymbolAddress((void**)&p_Ar, g_Ar);
    cudaGetSymbolAddress((void**)&p_Wr, g_Wr);
    cudaGetSymbolAddress((void**)&p_Wu, g_Wu);
    cudaGetSymbolAddress((void**)&p_Wd, g_Wd);
    cudaGetSymbolAddress((void**)&p_r,    g_r);
    cudaGetSymbolAddress((void**)&p_u,    g_u);
    cudaGetSymbolAddress((void**)&p_dpre, g_dpre);

    cudaFuncSetAttribute(gemm_mma_kernel,
                         cudaFuncAttributeMaxDynamicSharedMemorySize, GEMM_SMEM);

    const int ew_blocks = (BB * UU + 255) / 256;
    dim3 tb(32, 8);

    prep_kernel<<<ew_blocks, 256>>>(inputs, state);
    wconv_kernel<<<dim3(RU / 32, 32), tb>>>(W_r, p_Wr, RU);
    wconv_kernel<<<dim3(RU / 32, 32), tb>>>(W_u, p_Wu, RU);
    wconv_kernel<<<dim3(UU / 32, 32), tb>>>(W_d, p_Wd, UU);

    gemm_mma_kernel<<<dim3(RU / GBN, BB / GBM), 512, GEMM_SMEM>>>(p_Af, p_Wr, b_r, p_r, RU);
    gemm_mma_kernel<<<dim3(RU / GBN, BB / GBM), 512, GEMM_SMEM>>>(p_Af, p_Wu, b_u, p_u, RU);

    gate_r_kernel<<<ew_blocks, 256>>>(state);

    gemm_mma_kernel<<<dim3(UU / GBN, BB / GBM), 512, GEMM_SMEM>>>(p_Ar, p_Wd, b_d, p_dpre, UU);

    final_kernel<<<ew_blocks, 256>>>(state, elapsed, out_h, out_hh);
}

// round 13
// speedup vs baseline: 1.8246x; 1.1638x over previous
#include <cuda_runtime.h>
#include <cuda_bf16.h>
#include <cstdint>
#include <math.h>

// ---------------------------------------------------------------------------
// CT-GRU cell: B=2048, U=512, M=8, D=512, fused=1024
// Round 9: BK=128 (2x proven 64-wide subtiles), linearized loader addressing,
// 2-stage / 1 sync per iter, GEMM_d k-split x4, merged setup kernel.
// GEMMs: split-bf16 K'=3072 = [hi|hi|lo] x [hi|lo|hi], mma.sync m16n8k16.
// ---------------------------------------------------------------------------

#define BB 2048
#define UU 512
#define MM 8
#define DD 512
#define FD 1024
#define RU 4096          // U*M
#define KTOT 3072        // 3 * FD (split-K)

#define LN_TAU_STEP 1.1512925464970229f

// ---------------- scratch (allocation-free device globals) -----------------
__device__ __nv_bfloat16 g_Af[(size_t)BB * KTOT];     // fused'  [B, 3072]
__device__ __nv_bfloat16 g_Ar[(size_t)BB * KTOT];     // reset'  [B, 3072]
__device__ __nv_bfloat16 g_Wr[(size_t)RU * KTOT];     // W_r'^T  [4096, 3072]
__device__ __nv_bfloat16 g_Wu[(size_t)RU * KTOT];     // W_u'^T  [4096, 3072]
__device__ __nv_bfloat16 g_Wd[(size_t)UU * KTOT];     // W_d'^T  [512, 3072]
__device__ float g_r[(size_t)BB * RU];                // ln_tau_r
__device__ float g_u[(size_t)BB * RU];                // ln_tau_s
__device__ float g_dpre[4 * (size_t)BB * UU];         // pre-tanh k-split partials

// ---------------------------- asm helpers ----------------------------------
__device__ __forceinline__ uint32_t smem_u32(const void* p) {
    uint32_t a;
    asm("{ .reg .u64 t; cvta.to.shared.u64 t, %1; cvt.u32.u64 %0, t; }"
        : "=r"(a) : "l"(p));
    return a;
}

__device__ __forceinline__ void ldsm_x4(uint32_t* r, uint32_t addr) {
    asm volatile("ldmatrix.sync.aligned.m8n8.x4.shared.b16 {%0,%1,%2,%3}, [%4];"
        : "=r"(r[0]), "=r"(r[1]), "=r"(r[2]), "=r"(r[3]) : "r"(addr));
}

__device__ __forceinline__ void mma_bf16(float* d, const uint32_t* a,
                                         uint32_t b0, uint32_t b1) {
    asm volatile("mma.sync.aligned.m16n8k16.row.col.f32.bf16.bf16.f32 "
        "{%0,%1,%2,%3}, {%4,%5,%6,%7}, {%8,%9}, {%0,%1,%2,%3};"
        : "+f"(d[0]), "+f"(d[1]), "+f"(d[2]), "+f"(d[3])
        : "r"(a[0]), "r"(a[1]), "r"(a[2]), "r"(a[3]), "r"(b0), "r"(b1));
}

__device__ __forceinline__ void cp16(uint32_t dst, const void* src) {
    asm volatile("cp.async.cg.shared.global [%0], [%1], 16;"
                 :: "r"(dst), "l"(src));
}
#define CP_COMMIT() asm volatile("cp.async.commit_group;" ::: "memory")
#define CP_WAIT(n)  asm volatile("cp.async.wait_group %0;" :: "n"(n) : "memory")

// ---------------------------------------------------------------------------
// setup: z=0..2 -> weight convert/transpose (Wr, Wu, Wd); z=3 -> prep
// grid (128, 32, 4), block (32, 8)
// ---------------------------------------------------------------------------
__global__ void setup_kernel(const float* __restrict__ inputs,
                             const float* __restrict__ state,
                             const float* __restrict__ W_r,
                             const float* __restrict__ W_u,
                             const float* __restrict__ W_d)
{
    const int z = blockIdx.z;
    const int tx = threadIdx.x, ty = threadIdx.y;

    if (z == 3) {
        // ---- prep: h = sum_m h_hat; fused'/reset' bf16 splits ----
        int bl = blockIdx.y * 128 + blockIdx.x;
        int idx = bl * 256 + ty * 32 + tx;           // b*512 + j
        int b = idx >> 9;
        int j = idx & 511;

        float x = inputs[(size_t)b * DD + j];
        __nv_bfloat16 xh = __float2bfloat16_rn(x);
        __nv_bfloat16 xl = __float2bfloat16_rn(x - __bfloat162float(xh));

        size_t base = (size_t)b * KTOT;
        g_Af[base + j]        = xh;
        g_Af[base + 1024 + j] = xh;
        g_Af[base + 2048 + j] = xl;
        g_Ar[base + j]        = xh;
        g_Ar[base + 1024 + j] = xh;
        g_Ar[base + 2048 + j] = xl;

        const float* hp = state + (size_t)b * RU + j * MM;
        float4 h0 = *(const float4*)(hp);
        float4 h1 = *(const float4*)(hp + 4);
        float h = ((h0.x + h0.y) + (h0.z + h0.w)) + ((h1.x + h1.y) + (h1.z + h1.w));
        __nv_bfloat16 hh = __float2bfloat16_rn(h);
        __nv_bfloat16 hl = __float2bfloat16_rn(h - __bfloat162float(hh));
        g_Af[base + 512 + j]        = hh;
        g_Af[base + 1024 + 512 + j] = hh;
        g_Af[base + 2048 + 512 + j] = hl;
        return;
    }

    // ---- wconv plane: W[1024, Ndim] fp32 -> Wt[Ndim, 3072] bf16 [hi|lo|hi]
    const float* W;
    __nv_bfloat16* Wt;
    int Ndim;
    if (z == 0)      { W = W_r; Wt = g_Wr; Ndim = RU; }
    else if (z == 1) { W = W_u; Wt = g_Wu; Ndim = RU; }
    else             { W = W_d; Wt = g_Wd; Ndim = UU; }
    if (blockIdx.x * 32 >= Ndim) return;

    __shared__ float t[32][33];
    int n0 = blockIdx.x * 32;
    int k0 = blockIdx.y * 32;

#pragma unroll
    for (int i = 0; i < 4; i++) {
        int k = k0 + ty + i * 8;
        t[ty + i * 8][tx] = W[(size_t)k * Ndim + n0 + tx];
    }
    __syncthreads();

#pragma unroll
    for (int i = 0; i < 4; i++) {
        int r = ty + i * 8;
        float v = t[tx][r];
        __nv_bfloat16 vh = __float2bfloat16_rn(v);
        __nv_bfloat16 vl = __float2bfloat16_rn(v - __bfloat162float(vh));
        size_t base = (size_t)(n0 + r) * KTOT + k0 + tx;
        Wt[base]        = vh;
        Wt[base + 1024] = vl;
        Wt[base + 2048] = vh;
    }
}

// ---------------------------------------------------------------------------
// HMMA GEMM: C[2048, Ndim] = A'[2048,3072] @ Bt'[Ndim,3072]^T (+ bias)
// BM=256, BN=128, BK=128 (two 64-wide subtiles), 512 threads (16 warps 4x4),
// warp tile 64x32. 2-stage cp.async, ONE __syncthreads per K-iter.
// Optional k-split via blockIdx.z (kslice iters per slice, zstride on C).
// ---------------------------------------------------------------------------
#define GBM 256
#define GBN 128
#define GBK 128
#define NIT_FULL (KTOT / GBK)         // 24
#define STG_SUB 49152u                // per 64-subtile: A 32KB + B 16KB
#define STG   (2u * STG_SUB)          // 98304 per stage
#define GEMM_SMEM (2u * STG)          // 196608

__device__ __forceinline__ uint32_t swz(int row, int chunk) {
    return (uint32_t)(row * 128 + ((chunk ^ (row & 7)) << 4));
}

__global__ void __launch_bounds__(512, 1)
gemm_mma_kernel(const __nv_bfloat16* __restrict__ A,
                const __nv_bfloat16* __restrict__ Bt,
                const float* __restrict__ bias,
                float* __restrict__ C,
                int Ndim, int kslice, size_t zstride)
{
    extern __shared__ char smem[];
    const uint32_t sb = smem_u32(smem);
    const int tid = threadIdx.x;
    const int wid = tid >> 5;
    const int lane = tid & 31;
    const int bn = blockIdx.x * GBN;
    const int bm = blockIdx.y * GBM;
    const int kbeg = blockIdx.z * kslice;
    const int kend = kbeg + kslice;
    float* Cz = C + (size_t)blockIdx.z * zstride;

    const int warp_m = (wid & 3) * 64;      // 0,64,128,192
    const int warp_n = (wid >> 2) * 32;     // 0,32,64,96

    float acc[4][4][4];
#pragma unroll
    for (int i = 0; i < 4; i++)
#pragma unroll
        for (int j = 0; j < 4; j++)
#pragma unroll
            for (int v = 0; v < 4; v++) acc[i][j][v] = 0.0f;

    // ---- linearized loader state ----
    // granule slot s: row = (tid>>4) + 32*s, sub = (tid>>3)&1, ch = tid&7
    // (row & 7 invariant in s since 32 % 8 == 0 -> swizzle term constant)
    const int r0  = tid >> 4;                // 0..31
    const int sub = (tid >> 3) & 1;
    const int ch  = tid & 7;
    const uint32_t dstA = (uint32_t)sub * STG_SUB
                        + (uint32_t)(r0 * 128) + (uint32_t)((ch ^ (r0 & 7)) << 4);
    const uint32_t dstB = dstA + 32768u;
    // src byte offsets (row stride = KTOT*2 = 6144 B; per slot +32 rows)
    uint32_t a_src = (uint32_t)(r0 * 6144 + kbeg * 256 + sub * 128 + ch * 16);
    uint32_t b_src = a_src;
    const char* Abase = (const char*)A + (size_t)bm * (KTOT * 2);
    const char* Bbase = (const char*)Bt + (size_t)bn * (KTOT * 2);

    auto load_stage = [&](uint32_t stg_base) {
        const char* As = Abase + a_src;
#pragma unroll
        for (int s = 0; s < 8; s++)
            cp16(stg_base + dstA + (uint32_t)s * 4096u, As + (size_t)s * 196608);
        const char* Bs = Bbase + b_src;
#pragma unroll
        for (int s = 0; s < 4; s++)
            cp16(stg_base + dstB + (uint32_t)s * 4096u, Bs + (size_t)s * 196608);
        CP_COMMIT();
        a_src += 256; b_src += 256;          // advance to next K-chunk
    };

    load_stage(sb);                           // stage for iter kbeg -> buf 0

#pragma unroll 1
    for (int it = kbeg; it < kend; it++) {
        const uint32_t buf = (uint32_t)(it - kbeg) & 1u;
        CP_WAIT(0);
        __syncthreads();
        if (it + 1 < kend) load_stage(sb + (buf ^ 1u) * STG);

        const uint32_t cbase = sb + buf * STG;
#pragma unroll
        for (int sh = 0; sh < 2; sh++) {      // two 64-wide subtiles
            const uint32_t abase = cbase + (uint32_t)sh * STG_SUB;
            const uint32_t bbase = abase + 32768u;
#pragma unroll
            for (int kk = 0; kk < 4; kk++) {  // k-steps of 16
                const int kch = kk * 2;
                uint32_t a[4][4];
#pragma unroll
                for (int mi = 0; mi < 4; mi++) {
                    int row = warp_m + mi * 16 + (lane & 15);
                    int c = kch + ((lane >> 4) & 1);
                    ldsm_x4(a[mi], abase + swz(row, c));
                }
#pragma unroll
                for (int nb = 0; nb < 2; nb++) {
                    uint32_t b[4];
                    int row = warp_n + nb * 16 + (lane & 7) + (((lane >> 4) & 1) << 3);
                    int c = kch + ((lane >> 3) & 1);
                    ldsm_x4(b, bbase + swz(row, c));
#pragma unroll
                    for (int mi = 0; mi < 4; mi++) {
                        mma_bf16(acc[mi][nb * 2 + 0], a[mi], b[0], b[1]);
                        mma_bf16(acc[mi][nb * 2 + 1], a[mi], b[2], b[3]);
                    }
                }
            }
        }
        // no trailing sync: next iter's wait+sync precedes any overwrite
    }

    // ---- epilogue (+bias if given) ----
    const int q  = lane & 3;
    const int rq = lane >> 2;
#pragma unroll
    for (int ni = 0; ni < 4; ni++) {
        int col = bn + warp_n + ni * 8 + q * 2;
        float bv0 = 0.0f, bv1 = 0.0f;
        if (bias) { bv0 = bias[col]; bv1 = bias[col + 1]; }
#pragma unroll
        for (int mi = 0; mi < 4; mi++) {
            int rr = bm + warp_m + mi * 16 + rq;
            float2 v0 = make_float2(acc[mi][ni][0] + bv0, acc[mi][ni][1] + bv1);
            float2 v1 = make_float2(acc[mi][ni][2] + bv0, acc[mi][ni][3] + bv1);
            *(float2*)(Cz + (size_t)rr * Ndim + col) = v0;
            *(float2*)(Cz + (size_t)(rr + 8) * Ndim + col) = v1;
        }
    }
}

// ---------------------------------------------------------------------------
// gate_r: rki softmax + q_input; writes q (bf16 split) into reset' columns
// ---------------------------------------------------------------------------
__global__ void gate_r_kernel(const float* __restrict__ state)
{
    int idx = blockIdx.x * blockDim.x + threadIdx.x;
    if (idx >= BB * UU) return;
    int b = idx >> 9;
    int u = idx & 511;

    const float* rp = g_r + (size_t)b * RU + u * MM;
    float x[8];
    *(float4*)&x[0] = *(const float4*)(rp);
    *(float4*)&x[4] = *(const float4*)(rp + 4);

    const float* hp = state + (size_t)b * RU + u * MM;
    float h[8];
    *(float4*)&h[0] = *(const float4*)(hp);
    *(float4*)&h[4] = *(const float4*)(hp + 4);

    float e[8], mx = -1e30f;
#pragma unroll
    for (int m = 0; m < 8; m++) {
        float d = x[m] - LN_TAU_STEP * (float)m;
        e[m] = -d * d;
        mx = fmaxf(mx, e[m]);
    }
    float s = 0.0f, q = 0.0f;
#pragma unroll
    for (int m = 0; m < 8; m++) {
        float w = __expf(e[m] - mx);
        s += w;
        q = fmaf(w, h[m], q);
    }
    float qv = q / s;
    __nv_bfloat16 qh = __float2bfloat16_rn(qv);
    __nv_bfloat16 ql = __float2bfloat16_rn(qv - __bfloat162float(qh));
    size_t base = (size_t)b * KTOT;
    g_Ar[base + 512 + u]        = qh;
    g_Ar[base + 1024 + 512 + u] = qh;
    g_Ar[base + 2048 + 512 + u] = ql;
}

// ---------------------------------------------------------------------------
// final: dpre = sum of 4 k-split partials + b_d; qk=tanh; ski softmax; decay
// ---------------------------------------------------------------------------
__global__ void final_kernel(const float* __restrict__ state,
                             const float* __restrict__ elapsed,
                             const float* __restrict__ b_d,
                             float* __restrict__ out_h,
                             float* __restrict__ out_hh)
{
    int idx = blockIdx.x * blockDim.x + threadIdx.x;
    if (idx >= BB * UU) return;
    int b = idx >> 9;
    int u = idx & 511;

    const float invtau[8] = {1.0f, 0.31622776601683794f, 0.1f,
                             0.03162277660168379f, 0.01f,
                             0.003162277660168379f, 0.001f,
                             0.00031622776601683794f};

    const size_t NP = (size_t)BB * UU;
    float dpre = ((g_dpre[idx] + g_dpre[idx + NP])
               +  (g_dpre[idx + 2 * NP] + g_dpre[idx + 3 * NP])) + b_d[u];
    float qk = tanhf(dpre);

    const float* up = g_u + (size_t)b * RU + u * MM;
    float x[8];
    *(float4*)&x[0] = *(const float4*)(up);
    *(float4*)&x[4] = *(const float4*)(up + 4);

    const float* hp = state + (size_t)b * RU + u * MM;
    float h[8];
    *(float4*)&h[0] = *(const float4*)(hp);
    *(float4*)&h[4] = *(const float4*)(hp + 4);

    float e[8], mx = -1e30f;
#pragma unroll
    for (int m = 0; m < 8; m++) {
        float d = x[m] - LN_TAU_STEP * (float)m;
        e[m] = -d * d;
        mx = fmaxf(mx, e[m]);
    }
    float w[8], s = 0.0f;
#pragma unroll
    for (int m = 0; m < 8; m++) {
        w[m] = __expf(e[m] - mx);
        s += w[m];
    }
    float inv_s = 1.0f / s;
    float el = elapsed[b];

    float hh[8], hn = 0.0f;
#pragma unroll
    for (int m = 0; m < 8; m++) {
        float ski = w[m] * inv_s;
        float dec = __expf(-el * invtau[m]);
        hh[m] = ((1.0f - ski) * h[m] + ski * qk) * dec;
        hn += hh[m];
    }

    float* op = out_hh + (size_t)b * RU + u * MM;
    *(float4*)(op)     = *(const float4*)&hh[0];
    *(float4*)(op + 4) = *(const float4*)&hh[4];
    if (out_h) out_h[(size_t)b * UU + u] = hn;
}

// ---------------------------------------------------------------------------
// launch
// ---------------------------------------------------------------------------
extern "C" void kernel_launch(void* const* d_in, const int* in_sizes, int n_in,
                              void* d_out, int out_size)
{
    const float* inputs  = (const float*)d_in[0];
    const float* elapsed = (const float*)d_in[1];
    const float* state   = (const float*)d_in[2];
    const float* W_r     = (const float*)d_in[3];
    const float* b_r     = (const float*)d_in[4];
    const float* W_d     = (const float*)d_in[5];
    const float* b_d     = (const float*)d_in[6];
    const float* W_u     = (const float*)d_in[7];
    const float* b_u     = (const float*)d_in[8];

    float* out = (float*)d_out;
    float* out_h;
    float* out_hh;
    if (out_size == BB * UU * MM) {
        out_h = nullptr;
        out_hh = out;
    } else {
        out_h = out;
        out_hh = out + (size_t)BB * UU;
    }

    __nv_bfloat16 *p_Af, *p_Ar, *p_Wr, *p_Wu, *p_Wd;
    float *p_r, *p_u, *p_dpre;
    cudaGetSymbolAddress((void**)&p_Af, g_Af);
    cudaGetSymbolAddress((void**)&p_Ar, g_Ar);
    cudaGetSymbolAddress((void**)&p_Wr, g_Wr);
    cudaGetSymbolAddress((void**)&p_Wu, g_Wu);
    cudaGetSymbolAddress((void**)&p_Wd, g_Wd);
    cudaGetSymbolAddress((void**)&p_r,    g_r);
    cudaGetSymbolAddress((void**)&p_u,    g_u);
    cudaGetSymbolAddress((void**)&p_dpre, g_dpre);

    cudaFuncSetAttribute(gemm_mma_kernel,
                         cudaFuncAttributeMaxDynamicSharedMemorySize, GEMM_SMEM);

    const int ew_blocks = (BB * UU + 255) / 256;

    // setup: 3 wconv planes + prep plane
    setup_kernel<<<dim3(128, 32, 4), dim3(32, 8)>>>(inputs, state, W_r, W_u, W_d);

    // big GEMMs (full K, fused bias)
    gemm_mma_kernel<<<dim3(RU / GBN, BB / GBM, 1), 512, GEMM_SMEM>>>(
        p_Af, p_Wr, b_r, p_r, RU, NIT_FULL, 0);
    gemm_mma_kernel<<<dim3(RU / GBN, BB / GBM, 1), 512, GEMM_SMEM>>>(
        p_Af, p_Wu, b_u, p_u, RU, NIT_FULL, 0);

    gate_r_kernel<<<ew_blocks, 256>>>(state);

    // D GEMM: k-split x4 into partials (no bias; summed in final)
    gemm_mma_kernel<<<dim3(UU / GBN, BB / GBM, 4), 512, GEMM_SMEM>>>(
        p_Ar, p_Wd, nullptr, p_dpre, UU, NIT_FULL / 4, (size_t)BB * UU);

    final_kernel<<<ew_blocks, 256>>>(state, elapsed, b_d, out_h, out_hh);
}

// round 14
// speedup vs baseline: 1.8249x; 1.0002x over previous
#include <cuda_runtime.h>
#include <cuda_bf16.h>
#include <cstdint>
#include <math.h>

// ---------------------------------------------------------------------------
// CT-GRU cell: B=2048, U=512, M=8, D=512, fused=1024
// Round 9: BK=128 (2x proven 64-wide subtiles), linearized loader addressing,
// 2-stage / 1 sync per iter, GEMM_d k-split x4, merged setup kernel.
// GEMMs: split-bf16 K'=3072 = [hi|hi|lo] x [hi|lo|hi], mma.sync m16n8k16.
// ---------------------------------------------------------------------------

#define BB 2048
#define UU 512
#define MM 8
#define DD 512
#define FD 1024
#define RU 4096          // U*M
#define KTOT 3072        // 3 * FD (split-K)

#define LN_TAU_STEP 1.1512925464970229f

// ---------------- scratch (allocation-free device globals) -----------------
__device__ __nv_bfloat16 g_Af[(size_t)BB * KTOT];     // fused'  [B, 3072]
__device__ __nv_bfloat16 g_Ar[(size_t)BB * KTOT];     // reset'  [B, 3072]
__device__ __nv_bfloat16 g_Wr[(size_t)RU * KTOT];     // W_r'^T  [4096, 3072]
__device__ __nv_bfloat16 g_Wu[(size_t)RU * KTOT];     // W_u'^T  [4096, 3072]
__device__ __nv_bfloat16 g_Wd[(size_t)UU * KTOT];     // W_d'^T  [512, 3072]
__device__ float g_r[(size_t)BB * RU];                // ln_tau_r
__device__ float g_u[(size_t)BB * RU];                // ln_tau_s
__device__ float g_dpre[4 * (size_t)BB * UU];         // pre-tanh k-split partials

// ---------------------------- asm helpers ----------------------------------
__device__ __forceinline__ uint32_t smem_u32(const void* p) {
    uint32_t a;
    asm("{ .reg .u64 t; cvta.to.shared.u64 t, %1; cvt.u32.u64 %0, t; }"
        : "=r"(a) : "l"(p));
    return a;
}

__device__ __forceinline__ void ldsm_x4(uint32_t* r, uint32_t addr) {
    asm volatile("ldmatrix.sync.aligned.m8n8.x4.shared.b16 {%0,%1,%2,%3}, [%4];"
        : "=r"(r[0]), "=r"(r[1]), "=r"(r[2]), "=r"(r[3]) : "r"(addr));
}

__device__ __forceinline__ void mma_bf16(float* d, const uint32_t* a,
                                         uint32_t b0, uint32_t b1) {
    asm volatile("mma.sync.aligned.m16n8k16.row.col.f32.bf16.bf16.f32 "
        "{%0,%1,%2,%3}, {%4,%5,%6,%7}, {%8,%9}, {%0,%1,%2,%3};"
        : "+f"(d[0]), "+f"(d[1]), "+f"(d[2]), "+f"(d[3])
        : "r"(a[0]), "r"(a[1]), "r"(a[2]), "r"(a[3]), "r"(b0), "r"(b1));
}

__device__ __forceinline__ void cp16(uint32_t dst, const void* src) {
    asm volatile("cp.async.cg.shared.global [%0], [%1], 16;"
                 :: "r"(dst), "l"(src));
}
#define CP_COMMIT() asm volatile("cp.async.commit_group;" ::: "memory")
#define CP_WAIT(n)  asm volatile("cp.async.wait_group %0;" :: "n"(n) : "memory")

// ---------------------------------------------------------------------------
// setup: z=0..2 -> weight convert/transpose (Wr, Wu, Wd); z=3 -> prep
// grid (128, 32, 4), block (32, 8)
// ---------------------------------------------------------------------------
__global__ void setup_kernel(const float* __restrict__ inputs,
                             const float* __restrict__ state,
                             const float* __restrict__ W_r,
                             const float* __restrict__ W_u,
                             const float* __restrict__ W_d)
{
    const int z = blockIdx.z;
    const int tx = threadIdx.x, ty = threadIdx.y;

    if (z == 3) {
        // ---- prep: h = sum_m h_hat; fused'/reset' bf16 splits ----
        int bl = blockIdx.y * 128 + blockIdx.x;
        int idx = bl * 256 + ty * 32 + tx;           // b*512 + j
        int b = idx >> 9;
        int j = idx & 511;

        float x = inputs[(size_t)b * DD + j];
        __nv_bfloat16 xh = __float2bfloat16_rn(x);
        __nv_bfloat16 xl = __float2bfloat16_rn(x - __bfloat162float(xh));

        size_t base = (size_t)b * KTOT;
        g_Af[base + j]        = xh;
        g_Af[base + 1024 + j] = xh;
        g_Af[base + 2048 + j] = xl;
        g_Ar[base + j]        = xh;
        g_Ar[base + 1024 + j] = xh;
        g_Ar[base + 2048 + j] = xl;

        const float* hp = state + (size_t)b * RU + j * MM;
        float4 h0 = *(const float4*)(hp);
        float4 h1 = *(const float4*)(hp + 4);
        float h = ((h0.x + h0.y) + (h0.z + h0.w)) + ((h1.x + h1.y) + (h1.z + h1.w));
        __nv_bfloat16 hh = __float2bfloat16_rn(h);
        __nv_bfloat16 hl = __float2bfloat16_rn(h - __bfloat162float(hh));
        g_Af[base + 512 + j]        = hh;
        g_Af[base + 1024 + 512 + j] = hh;
        g_Af[base + 2048 + 512 + j] = hl;
        return;
    }

    // ---- wconv plane: W[1024, Ndim] fp32 -> Wt[Ndim, 3072] bf16 [hi|lo|hi]
    const float* W;
    __nv_bfloat16* Wt;
    int Ndim;
    if (z == 0)      { W = W_r; Wt = g_Wr; Ndim = RU; }
    else if (z == 1) { W = W_u; Wt = g_Wu; Ndim = RU; }
    else             { W = W_d; Wt = g_Wd; Ndim = UU; }
    if (blockIdx.x * 32 >= Ndim) return;

    __shared__ float t[32][33];
    int n0 = blockIdx.x * 32;
    int k0 = blockIdx.y * 32;

#pragma unroll
    for (int i = 0; i < 4; i++) {
        int k = k0 + ty + i * 8;
        t[ty + i * 8][tx] = W[(size_t)k * Ndim + n0 + tx];
    }
    __syncthreads();

#pragma unroll
    for (int i = 0; i < 4; i++) {
        int r = ty + i * 8;
        float v = t[tx][r];
        __nv_bfloat16 vh = __float2bfloat16_rn(v);
        __nv_bfloat16 vl = __float2bfloat16_rn(v - __bfloat162float(vh));
        size_t base = (size_t)(n0 + r) * KTOT + k0 + tx;
        Wt[base]        = vh;
        Wt[base + 1024] = vl;
        Wt[base + 2048] = vh;
    }
}

// ---------------------------------------------------------------------------
// HMMA GEMM: C[2048, Ndim] = A'[2048,3072] @ Bt'[Ndim,3072]^T (+ bias)
// BM=256, BN=128, BK=128 (two 64-wide subtiles), 512 threads (16 warps 4x4),
// warp tile 64x32. 2-stage cp.async, ONE __syncthreads per K-iter.
// Optional k-split via blockIdx.z (kslice iters per slice, zstride on C).
// ---------------------------------------------------------------------------
#define GBM 256
#define GBN 128
#define GBK 128
#define NIT_FULL (KTOT / GBK)         // 24
#define STG_SUB 49152u                // per 64-subtile: A 32KB + B 16KB
#define STG   (2u * STG_SUB)          // 98304 per stage
#define GEMM_SMEM (2u * STG)          // 196608

__device__ __forceinline__ uint32_t swz(int row, int chunk) {
    return (uint32_t)(row * 128 + ((chunk ^ (row & 7)) << 4));
}

__global__ void __launch_bounds__(512, 1)
gemm_mma_kernel(const __nv_bfloat16* __restrict__ A,
                const __nv_bfloat16* __restrict__ Bt,
                const float* __restrict__ bias,
                float* __restrict__ C,
                int Ndim, int kslice, size_t zstride)
{
    extern __shared__ char smem[];
    const uint32_t sb = smem_u32(smem);
    const int tid = threadIdx.x;
    const int wid = tid >> 5;
    const int lane = tid & 31;
    const int bn = blockIdx.x * GBN;
    const int bm = blockIdx.y * GBM;
    const int kbeg = blockIdx.z * kslice;
    const int kend = kbeg + kslice;
    float* Cz = C + (size_t)blockIdx.z * zstride;

    const int warp_m = (wid & 3) * 64;      // 0,64,128,192
    const int warp_n = (wid >> 2) * 32;     // 0,32,64,96

    float acc[4][4][4];
#pragma unroll
    for (int i = 0; i < 4; i++)
#pragma unroll
        for (int j = 0; j < 4; j++)
#pragma unroll
            for (int v = 0; v < 4; v++) acc[i][j][v] = 0.0f;

    // ---- linearized loader state ----
    // granule slot s: row = (tid>>4) + 32*s, sub = (tid>>3)&1, ch = tid&7
    // (row & 7 invariant in s since 32 % 8 == 0 -> swizzle term constant)
    const int r0  = tid >> 4;                // 0..31
    const int sub = (tid >> 3) & 1;
    const int ch  = tid & 7;
    const uint32_t dstA = (uint32_t)sub * STG_SUB
                        + (uint32_t)(r0 * 128) + (uint32_t)((ch ^ (r0 & 7)) << 4);
    const uint32_t dstB = dstA + 32768u;
    // src byte offsets (row stride = KTOT*2 = 6144 B; per slot +32 rows)
    uint32_t a_src = (uint32_t)(r0 * 6144 + kbeg * 256 + sub * 128 + ch * 16);
    uint32_t b_src = a_src;
    const char* Abase = (const char*)A + (size_t)bm * (KTOT * 2);
    const char* Bbase = (const char*)Bt + (size_t)bn * (KTOT * 2);

    auto load_stage = [&](uint32_t stg_base) {
        const char* As = Abase + a_src;
#pragma unroll
        for (int s = 0; s < 8; s++)
            cp16(stg_base + dstA + (uint32_t)s * 4096u, As + (size_t)s * 196608);
        const char* Bs = Bbase + b_src;
#pragma unroll
        for (int s = 0; s < 4; s++)
            cp16(stg_base + dstB + (uint32_t)s * 4096u, Bs + (size_t)s * 196608);
        CP_COMMIT();
        a_src += 256; b_src += 256;          // advance to next K-chunk
    };

    load_stage(sb);                           // stage for iter kbeg -> buf 0

#pragma unroll 1
    for (int it = kbeg; it < kend; it++) {
        const uint32_t buf = (uint32_t)(it - kbeg) & 1u;
        CP_WAIT(0);
        __syncthreads();
        if (it + 1 < kend) load_stage(sb + (buf ^ 1u) * STG);

        const uint32_t cbase = sb + buf * STG;
#pragma unroll
        for (int sh = 0; sh < 2; sh++) {      // two 64-wide subtiles
            const uint32_t abase = cbase + (uint32_t)sh * STG_SUB;
            const uint32_t bbase = abase + 32768u;
#pragma unroll
            for (int kk = 0; kk < 4; kk++) {  // k-steps of 16
                const int kch = kk * 2;
                uint32_t a[4][4];
#pragma unroll
                for (int mi = 0; mi < 4; mi++) {
                    int row = warp_m + mi * 16 + (lane & 15);
                    int c = kch + ((lane >> 4) & 1);
                    ldsm_x4(a[mi], abase + swz(row, c));
                }
#pragma unroll
                for (int nb = 0; nb < 2; nb++) {
                    uint32_t b[4];
                    int row = warp_n + nb * 16 + (lane & 7) + (((lane >> 4) & 1) << 3);
                    int c = kch + ((lane >> 3) & 1);
                    ldsm_x4(b, bbase + swz(row, c));
#pragma unroll
                    for (int mi = 0; mi < 4; mi++) {
                        mma_bf16(acc[mi][nb * 2 + 0], a[mi], b[0], b[1]);
                        mma_bf16(acc[mi][nb * 2 + 1], a[mi], b[2], b[3]);
                    }
                }
            }
        }
        // no trailing sync: next iter's wait+sync precedes any overwrite
    }

    // ---- epilogue (+bias if given) ----
    const int q  = lane & 3;
    const int rq = lane >> 2;
#pragma unroll
    for (int ni = 0; ni < 4; ni++) {
        int col = bn + warp_n + ni * 8 + q * 2;
        float bv0 = 0.0f, bv1 = 0.0f;
        if (bias) { bv0 = bias[col]; bv1 = bias[col + 1]; }
#pragma unroll
        for (int mi = 0; mi < 4; mi++) {
            int rr = bm + warp_m + mi * 16 + rq;
            float2 v0 = make_float2(acc[mi][ni][0] + bv0, acc[mi][ni][1] + bv1);
            float2 v1 = make_float2(acc[mi][ni][2] + bv0, acc[mi][ni][3] + bv1);
            *(float2*)(Cz + (size_t)rr * Ndim + col) = v0;
            *(float2*)(Cz + (size_t)(rr + 8) * Ndim + col) = v1;
        }
    }
}

// ---------------------------------------------------------------------------
// gate_r: rki softmax + q_input; writes q (bf16 split) into reset' columns
// ---------------------------------------------------------------------------
__global__ void gate_r_kernel(const float* __restrict__ state)
{
    int idx = blockIdx.x * blockDim.x + threadIdx.x;
    if (idx >= BB * UU) return;
    int b = idx >> 9;
    int u = idx & 511;

    const float* rp = g_r + (size_t)b * RU + u * MM;
    float x[8];
    *(float4*)&x[0] = *(const float4*)(rp);
    *(float4*)&x[4] = *(const float4*)(rp + 4);

    const float* hp = state + (size_t)b * RU + u * MM;
    float h[8];
    *(float4*)&h[0] = *(const float4*)(hp);
    *(float4*)&h[4] = *(const float4*)(hp + 4);

    float e[8], mx = -1e30f;
#pragma unroll
    for (int m = 0; m < 8; m++) {
        float d = x[m] - LN_TAU_STEP * (float)m;
        e[m] = -d * d;
        mx = fmaxf(mx, e[m]);
    }
    float s = 0.0f, q = 0.0f;
#pragma unroll
    for (int m = 0; m < 8; m++) {
        float w = __expf(e[m] - mx);
        s += w;
        q = fmaf(w, h[m], q);
    }
    float qv = q / s;
    __nv_bfloat16 qh = __float2bfloat16_rn(qv);
    __nv_bfloat16 ql = __float2bfloat16_rn(qv - __bfloat162float(qh));
    size_t base = (size_t)b * KTOT;
    g_Ar[base + 512 + u]        = qh;
    g_Ar[base + 1024 + 512 + u] = qh;
    g_Ar[base + 2048 + 512 + u] = ql;
}

// ---------------------------------------------------------------------------
// final: dpre = sum of 4 k-split partials + b_d; qk=tanh; ski softmax; decay
// ---------------------------------------------------------------------------
__global__ void final_kernel(const float* __restrict__ state,
                             const float* __restrict__ elapsed,
                             const float* __restrict__ b_d,
                             float* __restrict__ out_h,
                             float* __restrict__ out_hh)
{
    int idx = blockIdx.x * blockDim.x + threadIdx.x;
    if (idx >= BB * UU) return;
    int b = idx >> 9;
    int u = idx & 511;

    const float invtau[8] = {1.0f, 0.31622776601683794f, 0.1f,
                             0.03162277660168379f, 0.01f,
                             0.003162277660168379f, 0.001f,
                             0.00031622776601683794f};

    const size_t NP = (size_t)BB * UU;
    float dpre = ((g_dpre[idx] + g_dpre[idx + NP])
               +  (g_dpre[idx + 2 * NP] + g_dpre[idx + 3 * NP])) + b_d[u];
    float qk = tanhf(dpre);

    const float* up = g_u + (size_t)b * RU + u * MM;
    float x[8];
    *(float4*)&x[0] = *(const float4*)(up);
    *(float4*)&x[4] = *(const float4*)(up + 4);

    const float* hp = state + (size_t)b * RU + u * MM;
    float h[8];
    *(float4*)&h[0] = *(const float4*)(hp);
    *(float4*)&h[4] = *(const float4*)(hp + 4);

    float e[8], mx = -1e30f;
#pragma unroll
    for (int m = 0; m < 8; m++) {
        float d = x[m] - LN_TAU_STEP * (float)m;
        e[m] = -d * d;
        mx = fmaxf(mx, e[m]);
    }
    float w[8], s = 0.0f;
#pragma unroll
    for (int m = 0; m < 8; m++) {
        w[m] = __expf(e[m] - mx);
        s += w[m];
    }
    float inv_s = 1.0f / s;
    float el = elapsed[b];

    float hh[8], hn = 0.0f;
#pragma unroll
    for (int m = 0; m < 8; m++) {
        float ski = w[m] * inv_s;
        float dec = __expf(-el * invtau[m]);
        hh[m] = ((1.0f - ski) * h[m] + ski * qk) * dec;
        hn += hh[m];
    }

    float* op = out_hh + (size_t)b * RU + u * MM;
    *(float4*)(op)     = *(const float4*)&hh[0];
    *(float4*)(op + 4) = *(const float4*)&hh[4];
    if (out_h) out_h[(size_t)b * UU + u] = hn;
}

// ---------------------------------------------------------------------------
// launch
// ---------------------------------------------------------------------------
extern "C" void kernel_launch(void* const* d_in, const int* in_sizes, int n_in,
                              void* d_out, int out_size)
{
    const float* inputs  = (const float*)d_in[0];
    const float* elapsed = (const float*)d_in[1];
    const float* state   = (const float*)d_in[2];
    const float* W_r     = (const float*)d_in[3];
    const float* b_r     = (const float*)d_in[4];
    const float* W_d     = (const float*)d_in[5];
    const float* b_d     = (const float*)d_in[6];
    const float* W_u     = (const float*)d_in[7];
    const float* b_u     = (const float*)d_in[8];

    float* out = (float*)d_out;
    float* out_h;
    float* out_hh;
    if (out_size == BB * UU * MM) {
        out_h = nullptr;
        out_hh = out;
    } else {
        out_h = out;
        out_hh = out + (size_t)BB * UU;
    }

    __nv_bfloat16 *p_Af, *p_Ar, *p_Wr, *p_Wu, *p_Wd;
    float *p_r, *p_u, *p_dpre;
    cudaGetSymbolAddress((void**)&p_Af, g_Af);
    cudaGetSymbolAddress((void**)&p_Ar, g_Ar);
    cudaGetSymbolAddress((void**)&p_Wr, g_Wr);
    cudaGetSymbolAddress((void**)&p_Wu, g_Wu);
    cudaGetSymbolAddress((void**)&p_Wd, g_Wd);
    cudaGetSymbolAddress((void**)&p_r,    g_r);
    cudaGetSymbolAddress((void**)&p_u,    g_u);
    cudaGetSymbolAddress((void**)&p_dpre, g_dpre);

    cudaFuncSetAttribute(gemm_mma_kernel,
                         cudaFuncAttributeMaxDynamicSharedMemorySize, GEMM_SMEM);

    const int ew_blocks = (BB * UU + 255) / 256;

    // setup: 3 wconv planes + prep plane
    setup_kernel<<<dim3(128, 32, 4), dim3(32, 8)>>>(inputs, state, W_r, W_u, W_d);

    // big GEMMs (full K, fused bias)
    gemm_mma_kernel<<<dim3(RU / GBN, BB / GBM, 1), 512, GEMM_SMEM>>>(
        p_Af, p_Wr, b_r, p_r, RU, NIT_FULL, 0);
    gemm_mma_kernel<<<dim3(RU / GBN, BB / GBM, 1), 512, GEMM_SMEM>>>(
        p_Af, p_Wu, b_u, p_u, RU, NIT_FULL, 0);

    gate_r_kernel<<<ew_blocks, 256>>>(state);

    // D GEMM: k-split x4 into partials (no bias; summed in final)
    gemm_mma_kernel<<<dim3(UU / GBN, BB / GBM, 4), 512, GEMM_SMEM>>>(
        p_Ar, p_Wd, nullptr, p_dpre, UU, NIT_FULL / 4, (size_t)BB * UU);

    final_kernel<<<ew_blocks, 256>>>(state, elapsed, b_d, out_h, out_hh);
}